// round 1
// baseline (speedup 1.0000x reference)
#include <cuda_runtime.h>

// Problem constants
#define HN    16
#define AD    64
#define SQ    1024
#define NB    4
#define DM    1024
#define KREL  16
#define SN_EPS 1e-8f

// Scratch (device globals: no runtime allocation allowed)
__device__ float g_q[NB * HN * SQ * AD];     // [B,H,S,AD]
__device__ float g_k[NB * HN * SQ * AD];
__device__ float g_v[NB * HN * SQ * AD];
__device__ float g_ctx[NB * SQ * DM];        // [B,S,H*AD]

// ---------------------------------------------------------------------------
// SGEMM:  out[m,n] = sum_k A[m,k] * W[n,k] + bias[n]
// A row-major [M,K], W row-major [N,K]  (both K-contiguous)
// MODE 0: QKV projection -> scatter into g_q/g_k/g_v
// MODE 1: output projection, A is ignored (reads g_ctx), writes C row-major
// BM=BN=128, BK=16, 256 threads, 8x8 microtile
// ---------------------------------------------------------------------------
template <int MODE>
__global__ __launch_bounds__(256)
void sgemm_kernel(const float* __restrict__ A, const float* __restrict__ W,
                  const float* __restrict__ bias, float* __restrict__ C,
                  int M, int N, int K)
{
    __shared__ float As[16][132];   // [k][m], pad keeps float4 alignment (132%4==0)
    __shared__ float Bs[16][132];   // [k][n]

    const int tid = threadIdx.x;
    const int tx  = tid & 15;       // 0..15  (n-direction)
    const int ty  = tid >> 4;       // 0..15  (m-direction)
    const int rl  = tid >> 2;       // 0..63  load row
    const int c4  = (tid & 3) << 2; // 0,4,8,12 load col (float4)

    const float* Asrc = (MODE == 1) ? (const float*)g_ctx : A;

    const float* Ap = Asrc + (long)(blockIdx.y * 128 + rl) * K + c4;
    const float* Wp = W    + (long)(blockIdx.x * 128 + rl) * K + c4;

    float acc[8][8];
#pragma unroll
    for (int i = 0; i < 8; i++)
#pragma unroll
        for (int j = 0; j < 8; j++) acc[i][j] = 0.f;

    for (int k0 = 0; k0 < K; k0 += 16) {
        float4 a0 = *(const float4*)(Ap + k0);
        float4 a1 = *(const float4*)(Ap + k0 + (long)64 * K);
        float4 b0 = *(const float4*)(Wp + k0);
        float4 b1 = *(const float4*)(Wp + k0 + (long)64 * K);
        __syncthreads();   // guard against previous iteration's compute
        As[c4 + 0][rl] = a0.x; As[c4 + 1][rl] = a0.y; As[c4 + 2][rl] = a0.z; As[c4 + 3][rl] = a0.w;
        As[c4 + 0][rl + 64] = a1.x; As[c4 + 1][rl + 64] = a1.y; As[c4 + 2][rl + 64] = a1.z; As[c4 + 3][rl + 64] = a1.w;
        Bs[c4 + 0][rl] = b0.x; Bs[c4 + 1][rl] = b0.y; Bs[c4 + 2][rl] = b0.z; Bs[c4 + 3][rl] = b0.w;
        Bs[c4 + 0][rl + 64] = b1.x; Bs[c4 + 1][rl + 64] = b1.y; Bs[c4 + 2][rl + 64] = b1.z; Bs[c4 + 3][rl + 64] = b1.w;
        __syncthreads();
#pragma unroll
        for (int k = 0; k < 16; k++) {
            float4 af0 = *(const float4*)&As[k][ty * 8];
            float4 af1 = *(const float4*)&As[k][ty * 8 + 4];
            float4 bf0 = *(const float4*)&Bs[k][tx * 8];
            float4 bf1 = *(const float4*)&Bs[k][tx * 8 + 4];
            float av[8] = {af0.x, af0.y, af0.z, af0.w, af1.x, af1.y, af1.z, af1.w};
            float bv[8] = {bf0.x, bf0.y, bf0.z, bf0.w, bf1.x, bf1.y, bf1.z, bf1.w};
#pragma unroll
            for (int i = 0; i < 8; i++)
#pragma unroll
                for (int j = 0; j < 8; j++)
                    acc[i][j] = fmaf(av[i], bv[j], acc[i][j]);
        }
    }

    const int gcol = blockIdx.x * 128 + tx * 8;
    float4 bia0 = *(const float4*)(bias + gcol);
    float4 bia1 = *(const float4*)(bias + gcol + 4);

    if (MODE == 0) {
        // scatter into q/k/v [B,H,S,AD]; an 8-wide col strip never crosses a
        // which/head boundary (gcol % 64 + 8 <= 64)
        const int which = gcol >> 10;
        const int hh    = (gcol >> 6) & 15;
        const int dd    = gcol & 63;
        float* dst = (which == 0) ? g_q : ((which == 1) ? g_k : g_v);
#pragma unroll
        for (int i = 0; i < 8; i++) {
            int rr = blockIdx.y * 128 + ty * 8 + i;
            int bb = rr >> 10, ss = rr & 1023;
            float* p = dst + ((long)(bb * HN + hh) * SQ + ss) * AD + dd;
            float4 o0 = {acc[i][0] + bia0.x, acc[i][1] + bia0.y, acc[i][2] + bia0.z, acc[i][3] + bia0.w};
            float4 o1 = {acc[i][4] + bia1.x, acc[i][5] + bia1.y, acc[i][6] + bia1.z, acc[i][7] + bia1.w};
            *(float4*)p       = o0;
            *(float4*)(p + 4) = o1;
        }
    } else {
#pragma unroll
        for (int i = 0; i < 8; i++) {
            int rr = blockIdx.y * 128 + ty * 8 + i;
            float* p = C + (long)rr * N + gcol;
            float4 o0 = {acc[i][0] + bia0.x, acc[i][1] + bia0.y, acc[i][2] + bia0.z, acc[i][3] + bia0.w};
            float4 o1 = {acc[i][4] + bia1.x, acc[i][5] + bia1.y, acc[i][6] + bia1.z, acc[i][7] + bia1.w};
            *(float4*)p       = o0;
            *(float4*)(p + 4) = o1;
        }
    }
}

// ---------------------------------------------------------------------------
// Fused attention with SparseNormer (streaming; no score materialization).
// Grid: (S/64, H, B). Block: 256 threads. Per block: one 64-row q tile.
//   rq[r][p] = q_r . rel_emb[p]   (33 values/row; rel term = rq[r][clip(j-i)+16])
//   s   = (q k^T + rel) / 8 + sn_bias ;  t = relu(s)^2
//   num += t V ; den += rowsum(t) ;  ctx = num / (den + eps)
// ---------------------------------------------------------------------------
#define AT_STR 68   // smem row stride (float4-aligned, bank-skewed)

// float offsets into dynamic smem
#define OFF_QST   0                       // [64][AT_STR]  q transposed: [d][qr]
#define OFF_KST   (OFF_QST  + 64*AT_STR)  // [64][AT_STR]  k transposed: [d][kr]
#define OFF_VS    (OFF_KST  + 64*AT_STR)  // [64][AT_STR]  v row-major:  [kr][d]
#define OFF_TST   (OFF_VS   + 64*AT_STR)  // [64][AT_STR]  t transposed: [kr][qr]
#define OFF_RELS  (OFF_TST  + 64*AT_STR)  // [33][AT_STR]
#define OFF_RQS   (OFF_RELS + 33*AT_STR)  // [64][36]
#define OFF_DPART (OFF_RQS  + 64*36)      // [64][16]
#define OFF_DENS  (OFF_DPART+ 64*16)      // [64]
#define AT_SMEM_FLOATS (OFF_DENS + 64)
#define AT_SMEM_BYTES  (AT_SMEM_FLOATS * 4)

__global__ __launch_bounds__(256)
void attn_kernel(const float* __restrict__ rel_emb, const float* __restrict__ snb_p)
{
    extern __shared__ float sm[];
    float* qst   = sm + OFF_QST;
    float* kst   = sm + OFF_KST;
    float* vs    = sm + OFF_VS;
    float* tst   = sm + OFF_TST;
    float* rels  = sm + OFF_RELS;
    float* rqs   = sm + OFF_RQS;
    float* dpart = sm + OFF_DPART;
    float* dens  = sm + OFF_DENS;

    const int qt = blockIdx.x, h = blockIdx.y, b = blockIdx.z;
    const int tid = threadIdx.x;
    const int tx = tid & 15;    // key-col / dim-col direction (x4)
    const int ty = tid >> 4;    // q-row direction (x4)
    const float snb = __ldg(snb_p);

    const int bh = b * HN + h;
    const int q0 = qt * 64;
    const float* Qg = g_q + ((long)bh * SQ + q0) * AD;
    const float* Kg = g_k + (long)bh * SQ * AD;
    const float* Vg = g_v + (long)bh * SQ * AD;

    // load q tile transposed
    for (int i = tid; i < 64 * 16; i += 256) {
        int r = i >> 4, cc = (i & 15) << 2;
        float4 v = *(const float4*)(Qg + r * AD + cc);
        qst[(cc + 0) * AT_STR + r] = v.x;
        qst[(cc + 1) * AT_STR + r] = v.y;
        qst[(cc + 2) * AT_STR + r] = v.z;
        qst[(cc + 3) * AT_STR + r] = v.w;
    }
    // rel_emb [33][64]
    for (int i = tid; i < 33 * 16; i += 256) {
        int r = i >> 4, cc = (i & 15) << 2;
        *(float4*)&rels[r * AT_STR + cc] = *(const float4*)(rel_emb + r * 64 + cc);
    }
    __syncthreads();

    // rq[r][p] = q_r . rel_emb[p]
    for (int i = tid; i < 64 * 33; i += 256) {
        int r = i / 33, p = i - r * 33;
        float s = 0.f;
#pragma unroll 16
        for (int d = 0; d < 64; d++) s = fmaf(qst[d * AT_STR + r], rels[p * AT_STR + d], s);
        rqs[r * 36 + p] = s;
    }

    float num[4][4];
#pragma unroll
    for (int i = 0; i < 4; i++)
#pragma unroll
        for (int j = 0; j < 4; j++) num[i][j] = 0.f;
    float denloc[4] = {0.f, 0.f, 0.f, 0.f};

    for (int kt = 0; kt < 16; kt++) {
        __syncthreads();   // previous tile's num-GEMM done before overwrite
        for (int i = tid; i < 64 * 16; i += 256) {
            int r = i >> 4, cc = (i & 15) << 2;
            float4 kv = *(const float4*)(Kg + (long)(kt * 64 + r) * AD + cc);
            kst[(cc + 0) * AT_STR + r] = kv.x;
            kst[(cc + 1) * AT_STR + r] = kv.y;
            kst[(cc + 2) * AT_STR + r] = kv.z;
            kst[(cc + 3) * AT_STR + r] = kv.w;
            *(float4*)&vs[r * AT_STR + cc] = *(const float4*)(Vg + (long)(kt * 64 + r) * AD + cc);
        }
        __syncthreads();

        // s = q k^T (4x4 microtile)
        float sacc[4][4];
#pragma unroll
        for (int i = 0; i < 4; i++)
#pragma unroll
            for (int j = 0; j < 4; j++) sacc[i][j] = 0.f;
#pragma unroll 16
        for (int d = 0; d < 64; d++) {
            float4 aq = *(const float4*)&qst[d * AT_STR + ty * 4];
            float4 bk = *(const float4*)&kst[d * AT_STR + tx * 4];
            float av[4] = {aq.x, aq.y, aq.z, aq.w};
            float bv[4] = {bk.x, bk.y, bk.z, bk.w};
#pragma unroll
            for (int i = 0; i < 4; i++)
#pragma unroll
                for (int j = 0; j < 4; j++)
                    sacc[i][j] = fmaf(av[i], bv[j], sacc[i][j]);
        }

        // t = relu((s + rel)/8 + b)^2 -> tst (transposed), accumulate den
#pragma unroll
        for (int i = 0; i < 4; i++) {
            int qr = ty * 4 + i;
            int ig = q0 + qr;
#pragma unroll
            for (int j = 0; j < 4; j++) {
                int kc = tx * 4 + j;
                int jg = kt * 64 + kc;
                int dlt = jg - ig;
                dlt = (dlt < -KREL) ? -KREL : ((dlt > KREL) ? KREL : dlt);
                float sv = (sacc[i][j] + rqs[qr * 36 + dlt + KREL]) * 0.125f + snb;
                sv = fmaxf(sv, 0.f);
                sv = sv * sv;
                tst[kc * AT_STR + qr] = sv;
                denloc[i] += sv;
            }
        }
        __syncthreads();

        // num += t V (4x4 microtile over [qr][dim])
#pragma unroll 16
        for (int k = 0; k < 64; k++) {
            float4 at = *(const float4*)&tst[k * AT_STR + ty * 4];
            float4 bv4 = *(const float4*)&vs[k * AT_STR + tx * 4];
            float av[4] = {at.x, at.y, at.z, at.w};
            float bv[4] = {bv4.x, bv4.y, bv4.z, bv4.w};
#pragma unroll
            for (int i = 0; i < 4; i++)
#pragma unroll
                for (int j = 0; j < 4; j++)
                    num[i][j] = fmaf(av[i], bv[j], num[i][j]);
        }
    }

    // deterministic den reduction
#pragma unroll
    for (int i = 0; i < 4; i++) dpart[(ty * 4 + i) * 16 + tx] = denloc[i];
    __syncthreads();
    if (tid < 64) {
        float s = 0.f;
#pragma unroll
        for (int j = 0; j < 16; j++) s += dpart[tid * 16 + j];
        dens[tid] = s;
    }
    __syncthreads();

    // ctx[b, q0+r, h*64 + d] = num / (den + eps)
#pragma unroll
    for (int i = 0; i < 4; i++) {
        int r = ty * 4 + i;
        float inv = 1.f / (dens[r] + SN_EPS);
        float4 o = {num[i][0] * inv, num[i][1] * inv, num[i][2] * inv, num[i][3] * inv};
        *(float4*)&g_ctx[((long)(b * SQ + q0 + r)) * DM + h * AD + tx * 4] = o;
    }
}

// ---------------------------------------------------------------------------
extern "C" void kernel_launch(void* const* d_in, const int* in_sizes, int n_in,
                              void* d_out, int out_size)
{
    (void)in_sizes; (void)n_in; (void)out_size;
    const float* iQ  = (const float*)d_in[0];
    const float* Wa  = (const float*)d_in[1];
    const float* ba  = (const float*)d_in[2];
    const float* rel = (const float*)d_in[3];
    const float* snb = (const float*)d_in[4];
    const float* Wo  = (const float*)d_in[5];
    const float* bo  = (const float*)d_in[6];
    float* out = (float*)d_out;

    cudaFuncSetAttribute(attn_kernel, cudaFuncAttributeMaxDynamicSharedMemorySize, AT_SMEM_BYTES);

    // 1) QKV projection: [4096,1024] x [3072,1024]^T -> scatter to g_q/g_k/g_v
    sgemm_kernel<0><<<dim3(3072 / 128, 4096 / 128), 256>>>(iQ, Wa, ba, nullptr, 4096, 3072, 1024);

    // 2) fused relative-position attention + SparseNormer -> g_ctx
    attn_kernel<<<dim3(SQ / 64, HN, NB), 256, AT_SMEM_BYTES>>>(rel, snb);

    // 3) output projection: g_ctx [4096,1024] x Wo[1024,1024]^T + bo -> out
    sgemm_kernel<1><<<dim3(1024 / 128, 4096 / 128), 256>>>(nullptr, Wo, bo, out, 4096, 1024, 1024);
}

// round 7
// speedup vs baseline: 1.2141x; 1.2141x over previous
#include <cuda_runtime.h>
#include <cstdint>

// Problem constants
#define HN    16
#define AD    64
#define SQ    1024
#define NB    4
#define DM    1024
#define KREL  16
#define SN_EPS 1e-8f

// Scratch (device globals: no runtime allocation allowed)
__device__ __align__(16) float g_q[NB * HN * SQ * AD];     // [B,H,S,AD]
__device__ __align__(16) float g_k[NB * HN * SQ * AD];
__device__ __align__(16) float g_v[NB * HN * SQ * AD];
__device__ __align__(16) float g_ctx[NB * SQ * DM];        // [B,S,H*AD]

// ===========================================================================
// Helpers (baseline sm_80+ PTX only)
// ===========================================================================
__device__ __forceinline__ void cp16(uint32_t saddr, const void* g) {
    asm volatile("cp.async.cg.shared.global [%0], [%1], 16;\n" :: "r"(saddr), "l"(g));
}
#define CP_COMMIT() asm volatile("cp.async.commit_group;\n" ::: "memory")
#define CP_WAIT(n)  asm volatile("cp.async.wait_group %0;\n" :: "n"(n) : "memory")

__device__ __forceinline__ uint32_t smem_u32(const void* p) {
    uint32_t a;
    asm("{ .reg .u64 t; cvta.to.shared.u64 t, %1; cvt.u32.u64 %0, t; }"
        : "=r"(a) : "l"(p));
    return a;
}

__device__ __forceinline__ void mma_tf32(float c[4], const uint32_t a[4], const uint32_t b[2]) {
    asm volatile(
        "mma.sync.aligned.m16n8k8.row.col.f32.tf32.tf32.f32 "
        "{%0,%1,%2,%3}, {%4,%5,%6,%7}, {%8,%9}, {%0,%1,%2,%3};"
        : "+f"(c[0]), "+f"(c[1]), "+f"(c[2]), "+f"(c[3])
        : "r"(a[0]), "r"(a[1]), "r"(a[2]), "r"(a[3]), "r"(b[0]), "r"(b[1]));
}

// split: hi = top-10-mantissa (exactly tf32), lo = x - hi (|lo| <= 2^-10 |x|)
__device__ __forceinline__ void tf32_split(float x, uint32_t& hi, uint32_t& lo) {
    hi = __float_as_uint(x) & 0xFFFFE000u;
    lo = __float_as_uint(x - __uint_as_float(hi));
}

// ===========================================================================
// 3xTF32 mma.sync GEMM:  C[m,n] = sum_k A[m,k] * W[n,k] + bias[n]
// A row-major [M,K], W row-major [N,K] (C = A * W^T; "row.col" mma).
// BM=BN=128, BK=32, 256 threads (8 warps, 2x4), warp tile 64x32,
// 4x4 m16n8k8 fragments, each computed as Ah*Bh + Ah*Bl + Al*Bh (fp32-accurate).
// cp.async double buffer. Rows padded to 36 floats (conflict-free frag LDS).
// MODE 0: QKV projection (A = iQ), scatter into g_q/g_k/g_v
// MODE 1: output projection (A = g_ctx), dense row-major C
// ===========================================================================
#define GK      1024
#define BKC     32
#define ROWF    36
#define TILE_F  (128 * ROWF)
#define GSM_FLOATS (4 * TILE_F)            // A0,W0,A1,W1
#define GSM_BYTES  (GSM_FLOATS * 4)

template <int MODE>
__global__ __launch_bounds__(256, 2)
void tc_gemm(const float* __restrict__ A_in, const float* __restrict__ W,
             const float* __restrict__ bias, float* __restrict__ C, int N)
{
    extern __shared__ __align__(16) float smem[];
    float* sA[2] = { smem,              smem + 2 * TILE_F };
    float* sW[2] = { smem + TILE_F,     smem + 3 * TILE_F };

    const int tid  = threadIdx.x;
    const int wid  = tid >> 5;
    const int lane = tid & 31;
    const int g    = lane >> 2;        // 0..7
    const int tig  = lane & 3;         // 0..3
    const int wm   = wid >> 2;         // 0..1 (m)
    const int wn   = wid & 3;          // 0..3 (n)
    const int mbase = wm * 64;
    const int nbase = wn * 32;

    const int bx = blockIdx.x;         // N tile
    const int by = blockIdx.y;         // M tile

    const float* A = (MODE == 1) ? (const float*)g_ctx : A_in;
    const float* Abase = A + (long)(by * 128) * GK;
    const float* Wbase = W + (long)(bx * 128) * GK;

    const uint32_t sbase = smem_u32(smem);
    auto load_chunk = [&](int kc, int buf) {
        const uint32_t aoff = sbase + (uint32_t)((buf ? 2 * TILE_F : 0) * 4);
        const uint32_t woff = sbase + (uint32_t)(((buf ? 3 * TILE_F : TILE_F)) * 4);
#pragma unroll
        for (int i = 0; i < 4; i++) {
            int idx = tid + i * 256;       // 0..1023
            int r = idx >> 3;              // row 0..127
            int q = idx & 7;               // float4 in row
            uint32_t so = (uint32_t)((r * ROWF + q * 4) * 4);
            cp16(aoff + so, Abase + (long)r * GK + kc * BKC + q * 4);
            cp16(woff + so, Wbase + (long)r * GK + kc * BKC + q * 4);
        }
    };

    float acc[4][4][4];
#pragma unroll
    for (int mi = 0; mi < 4; mi++)
#pragma unroll
        for (int ni = 0; ni < 4; ni++)
#pragma unroll
            for (int r = 0; r < 4; r++) acc[mi][ni][r] = 0.f;

    load_chunk(0, 0); CP_COMMIT();
    load_chunk(1, 1); CP_COMMIT();

    const int NCH = GK / BKC;          // 32
    for (int k0 = 0; k0 < NCH; k0++) {
        const int buf = k0 & 1;
        if (k0 + 1 < NCH) { CP_WAIT(1); } else { CP_WAIT(0); }
        __syncthreads();

        const float* As = sA[buf];
        const float* Ws = sW[buf];
#pragma unroll
        for (int kk = 0; kk < 4; kk++) {
            const int k8 = kk * 8;
            // B fragments: split once per kk
            uint32_t bh[4][2], bl[4][2];
#pragma unroll
            for (int ni = 0; ni < 4; ni++) {
                const int r0 = nbase + ni * 8 + g;
                tf32_split(Ws[r0 * ROWF + k8 + tig],     bh[ni][0], bl[ni][0]);
                tf32_split(Ws[r0 * ROWF + k8 + tig + 4], bh[ni][1], bl[ni][1]);
            }
#pragma unroll
            for (int mi = 0; mi < 4; mi++) {
                const int r0 = mbase + mi * 16 + g;
                uint32_t ah[4], al[4];
                tf32_split(As[r0 * ROWF + k8 + tig],           ah[0], al[0]);
                tf32_split(As[(r0 + 8) * ROWF + k8 + tig],     ah[1], al[1]);
                tf32_split(As[r0 * ROWF + k8 + tig + 4],       ah[2], al[2]);
                tf32_split(As[(r0 + 8) * ROWF + k8 + tig + 4], ah[3], al[3]);
#pragma unroll
                for (int ni = 0; ni < 4; ni++) {
                    mma_tf32(acc[mi][ni], ah, bh[ni]);   // hi*hi
                    mma_tf32(acc[mi][ni], ah, bl[ni]);   // hi*lo
                    mma_tf32(acc[mi][ni], al, bh[ni]);   // lo*hi
                }
            }
        }
        __syncthreads();
        if (k0 + 2 < NCH) { load_chunk(k0 + 2, buf); CP_COMMIT(); }
    }

    // Epilogue. c-fragment (m16n8): rows g, g+8; cols 2*tig, 2*tig+1.
#pragma unroll
    for (int ni = 0; ni < 4; ni++) {
        const int gcol = bx * 128 + nbase + ni * 8 + 2 * tig;
        const float b0 = bias[gcol];
        const float b1 = bias[gcol + 1];
        // scatter indices depend only on gcol (hoisted out of mi/h loops)
        const int which = gcol >> 10;
        const int hh = (gcol >> 6) & 15;
        const int dd = gcol & 63;
        float* dst = (MODE == 0)
                   ? ((which == 0) ? g_q : ((which == 1) ? g_k : g_v))
                   : C;
#pragma unroll
        for (int mi = 0; mi < 4; mi++) {
#pragma unroll
            for (int h = 0; h < 2; h++) {
                const int rr = by * 128 + mbase + mi * 16 + g + h * 8;
                float2 o;
                o.x = acc[mi][ni][2 * h + 0] + b0;
                o.y = acc[mi][ni][2 * h + 1] + b1;
                if (MODE == 0) {
                    const int bb = rr >> 10, ss = rr & 1023;
                    *(float2*)(dst + ((long)(bb * HN + hh) * SQ + ss) * AD + dd) = o;
                } else {
                    *(float2*)(dst + (long)rr * N + gcol) = o;
                }
            }
        }
    }
}

// ===========================================================================
// Fused attention with SparseNormer (round-1 known good, unchanged)
// ===========================================================================
#define AT_STR 68

#define OFF_QST   0
#define OFF_KST   (OFF_QST  + 64*AT_STR)
#define OFF_VS    (OFF_KST  + 64*AT_STR)
#define OFF_TST   (OFF_VS   + 64*AT_STR)
#define OFF_RELS  (OFF_TST  + 64*AT_STR)
#define OFF_RQS   (OFF_RELS + 33*AT_STR)
#define OFF_DPART (OFF_RQS  + 64*36)
#define OFF_DENS  (OFF_DPART+ 64*16)
#define AT_SMEM_FLOATS (OFF_DENS + 64)
#define AT_SMEM_BYTES  (AT_SMEM_FLOATS * 4)

__global__ __launch_bounds__(256)
void attn_kernel(const float* __restrict__ rel_emb, const float* __restrict__ snb_p)
{
    extern __shared__ float sm[];
    float* qst   = sm + OFF_QST;
    float* kst   = sm + OFF_KST;
    float* vs    = sm + OFF_VS;
    float* tst   = sm + OFF_TST;
    float* rels  = sm + OFF_RELS;
    float* rqs   = sm + OFF_RQS;
    float* dpart = sm + OFF_DPART;
    float* dens  = sm + OFF_DENS;

    const int qt = blockIdx.x, h = blockIdx.y, b = blockIdx.z;
    const int tid = threadIdx.x;
    const int tx = tid & 15;
    const int ty = tid >> 4;
    const float snb = __ldg(snb_p);

    const int bh = b * HN + h;
    const int q0 = qt * 64;
    const float* Qg = g_q + ((long)bh * SQ + q0) * AD;
    const float* Kg = g_k + (long)bh * SQ * AD;
    const float* Vg = g_v + (long)bh * SQ * AD;

    for (int i = tid; i < 64 * 16; i += 256) {
        int r = i >> 4, cc = (i & 15) << 2;
        float4 v = *(const float4*)(Qg + r * AD + cc);
        qst[(cc + 0) * AT_STR + r] = v.x;
        qst[(cc + 1) * AT_STR + r] = v.y;
        qst[(cc + 2) * AT_STR + r] = v.z;
        qst[(cc + 3) * AT_STR + r] = v.w;
    }
    for (int i = tid; i < 33 * 16; i += 256) {
        int r = i >> 4, cc = (i & 15) << 2;
        *(float4*)&rels[r * AT_STR + cc] = *(const float4*)(rel_emb + r * 64 + cc);
    }
    __syncthreads();

    for (int i = tid; i < 64 * 33; i += 256) {
        int r = i / 33, p = i - r * 33;
        float s = 0.f;
#pragma unroll 16
        for (int d = 0; d < 64; d++) s = fmaf(qst[d * AT_STR + r], rels[p * AT_STR + d], s);
        rqs[r * 36 + p] = s;
    }

    float num[4][4];
#pragma unroll
    for (int i = 0; i < 4; i++)
#pragma unroll
        for (int j = 0; j < 4; j++) num[i][j] = 0.f;
    float denloc[4] = {0.f, 0.f, 0.f, 0.f};

    for (int kt = 0; kt < 16; kt++) {
        __syncthreads();
        for (int i = tid; i < 64 * 16; i += 256) {
            int r = i >> 4, cc = (i & 15) << 2;
            float4 kv = *(const float4*)(Kg + (long)(kt * 64 + r) * AD + cc);
            kst[(cc + 0) * AT_STR + r] = kv.x;
            kst[(cc + 1) * AT_STR + r] = kv.y;
            kst[(cc + 2) * AT_STR + r] = kv.z;
            kst[(cc + 3) * AT_STR + r] = kv.w;
            *(float4*)&vs[r * AT_STR + cc] = *(const float4*)(Vg + (long)(kt * 64 + r) * AD + cc);
        }
        __syncthreads();

        float sacc[4][4];
#pragma unroll
        for (int i = 0; i < 4; i++)
#pragma unroll
            for (int j = 0; j < 4; j++) sacc[i][j] = 0.f;
#pragma unroll 16
        for (int d = 0; d < 64; d++) {
            float4 aq = *(const float4*)&qst[d * AT_STR + ty * 4];
            float4 bk = *(const float4*)&kst[d * AT_STR + tx * 4];
            float av[4] = {aq.x, aq.y, aq.z, aq.w};
            float bv[4] = {bk.x, bk.y, bk.z, bk.w};
#pragma unroll
            for (int i = 0; i < 4; i++)
#pragma unroll
                for (int j = 0; j < 4; j++)
                    sacc[i][j] = fmaf(av[i], bv[j], sacc[i][j]);
        }

#pragma unroll
        for (int i = 0; i < 4; i++) {
            int qr = ty * 4 + i;
            int ig = q0 + qr;
#pragma unroll
            for (int j = 0; j < 4; j++) {
                int kc = tx * 4 + j;
                int jg = kt * 64 + kc;
                int dlt = jg - ig;
                dlt = (dlt < -KREL) ? -KREL : ((dlt > KREL) ? KREL : dlt);
                float sv = (sacc[i][j] + rqs[qr * 36 + dlt + KREL]) * 0.125f + snb;
                sv = fmaxf(sv, 0.f);
                sv = sv * sv;
                tst[kc * AT_STR + qr] = sv;
                denloc[i] += sv;
            }
        }
        __syncthreads();

#pragma unroll 16
        for (int k = 0; k < 64; k++) {
            float4 at = *(const float4*)&tst[k * AT_STR + ty * 4];
            float4 bv4 = *(const float4*)&vs[k * AT_STR + tx * 4];
            float av[4] = {at.x, at.y, at.z, at.w};
            float bv[4] = {bv4.x, bv4.y, bv4.z, bv4.w};
#pragma unroll
            for (int i = 0; i < 4; i++)
#pragma unroll
                for (int j = 0; j < 4; j++)
                    num[i][j] = fmaf(av[i], bv[j], num[i][j]);
        }
    }

#pragma unroll
    for (int i = 0; i < 4; i++) dpart[(ty * 4 + i) * 16 + tx] = denloc[i];
    __syncthreads();
    if (tid < 64) {
        float s = 0.f;
#pragma unroll
        for (int j = 0; j < 16; j++) s += dpart[tid * 16 + j];
        dens[tid] = s;
    }
    __syncthreads();

#pragma unroll
    for (int i = 0; i < 4; i++) {
        int r = ty * 4 + i;
        float inv = 1.f / (dens[r] + SN_EPS);
        float4 o = {num[i][0] * inv, num[i][1] * inv, num[i][2] * inv, num[i][3] * inv};
        *(float4*)&g_ctx[((long)(b * SQ + q0 + r)) * DM + h * AD + tx * 4] = o;
    }
}

// ===========================================================================
extern "C" void kernel_launch(void* const* d_in, const int* in_sizes, int n_in,
                              void* d_out, int out_size)
{
    (void)in_sizes; (void)n_in; (void)out_size;
    const float* iQ  = (const float*)d_in[0];
    const float* Wa  = (const float*)d_in[1];
    const float* ba  = (const float*)d_in[2];
    const float* rel = (const float*)d_in[3];
    const float* snb = (const float*)d_in[4];
    const float* Wo  = (const float*)d_in[5];
    const float* bo  = (const float*)d_in[6];
    float* out = (float*)d_out;

    cudaFuncSetAttribute(tc_gemm<0>, cudaFuncAttributeMaxDynamicSharedMemorySize, GSM_BYTES);
    cudaFuncSetAttribute(tc_gemm<1>, cudaFuncAttributeMaxDynamicSharedMemorySize, GSM_BYTES);
    cudaFuncSetAttribute(attn_kernel, cudaFuncAttributeMaxDynamicSharedMemorySize, AT_SMEM_BYTES);

    // 1) QKV projection (3xTF32 mma.sync)
    tc_gemm<0><<<dim3(3072 / 128, 4096 / 128), 256, GSM_BYTES>>>(iQ, Wa, ba, nullptr, 3072);

    // 2) fused relative-position attention + SparseNormer -> g_ctx
    attn_kernel<<<dim3(SQ / 64, HN, NB), 256, AT_SMEM_BYTES>>>(rel, snb);

    // 3) output projection (3xTF32 mma.sync)
    tc_gemm<1><<<dim3(1024 / 128, 4096 / 128), 256, GSM_BYTES>>>(nullptr, Wo, bo, out, 1024);
}

// round 9
// speedup vs baseline: 1.5210x; 1.2527x over previous
#include <cuda_runtime.h>
#include <cstdint>

// Problem constants
#define HN    16
#define AD    64
#define SQ    1024
#define NB    4
#define DM    1024
#define KREL  16
#define SN_EPS 1e-8f

// Scratch (device globals: no runtime allocation allowed)
__device__ __align__(16) float g_q[NB * HN * SQ * AD];     // [B,H,S,AD]
__device__ __align__(16) float g_k[NB * HN * SQ * AD];
__device__ __align__(16) float g_v[NB * HN * SQ * AD];
__device__ __align__(16) float g_ctx[NB * SQ * DM];        // [B,S,H*AD]

// ===========================================================================
// Helpers (baseline sm_80+ PTX only)
// ===========================================================================
__device__ __forceinline__ void cp16(uint32_t saddr, const void* g) {
    asm volatile("cp.async.cg.shared.global [%0], [%1], 16;\n" :: "r"(saddr), "l"(g));
}
#define CP_COMMIT() asm volatile("cp.async.commit_group;\n" ::: "memory")
#define CP_WAIT(n)  asm volatile("cp.async.wait_group %0;\n" :: "n"(n) : "memory")

__device__ __forceinline__ uint32_t smem_u32(const void* p) {
    uint32_t a;
    asm("{ .reg .u64 t; cvta.to.shared.u64 t, %1; cvt.u32.u64 %0, t; }"
        : "=r"(a) : "l"(p));
    return a;
}

__device__ __forceinline__ void mma_tf32(float c[4], const uint32_t a[4], const uint32_t b[2]) {
    asm volatile(
        "mma.sync.aligned.m16n8k8.row.col.f32.tf32.tf32.f32 "
        "{%0,%1,%2,%3}, {%4,%5,%6,%7}, {%8,%9}, {%0,%1,%2,%3};"
        : "+f"(c[0]), "+f"(c[1]), "+f"(c[2]), "+f"(c[3])
        : "r"(a[0]), "r"(a[1]), "r"(a[2]), "r"(a[3]), "r"(b[0]), "r"(b[1]));
}

// split: hi = top-10-mantissa (exactly tf32), lo = x - hi (|lo| <= 2^-10 |x|)
__device__ __forceinline__ void tf32_split(float x, uint32_t& hi, uint32_t& lo) {
    hi = __float_as_uint(x) & 0xFFFFE000u;
    lo = __float_as_uint(x - __uint_as_float(hi));
}

// ===========================================================================
// 3xTF32 mma.sync GEMM (unchanged from round 7 — known good, 60% tensor)
// ===========================================================================
#define GK      1024
#define BKC     32
#define ROWF    36
#define TILE_F  (128 * ROWF)
#define GSM_FLOATS (4 * TILE_F)
#define GSM_BYTES  (GSM_FLOATS * 4)

template <int MODE>
__global__ __launch_bounds__(256, 2)
void tc_gemm(const float* __restrict__ A_in, const float* __restrict__ W,
             const float* __restrict__ bias, float* __restrict__ C, int N)
{
    extern __shared__ __align__(16) float smem[];
    float* sA[2] = { smem,              smem + 2 * TILE_F };
    float* sW[2] = { smem + TILE_F,     smem + 3 * TILE_F };

    const int tid  = threadIdx.x;
    const int wid  = tid >> 5;
    const int lane = tid & 31;
    const int g    = lane >> 2;
    const int tig  = lane & 3;
    const int wm   = wid >> 2;
    const int wn   = wid & 3;
    const int mbase = wm * 64;
    const int nbase = wn * 32;

    const int bx = blockIdx.x;
    const int by = blockIdx.y;

    const float* A = (MODE == 1) ? (const float*)g_ctx : A_in;
    const float* Abase = A + (long)(by * 128) * GK;
    const float* Wbase = W + (long)(bx * 128) * GK;

    const uint32_t sbase = smem_u32(smem);
    auto load_chunk = [&](int kc, int buf) {
        const uint32_t aoff = sbase + (uint32_t)((buf ? 2 * TILE_F : 0) * 4);
        const uint32_t woff = sbase + (uint32_t)(((buf ? 3 * TILE_F : TILE_F)) * 4);
#pragma unroll
        for (int i = 0; i < 4; i++) {
            int idx = tid + i * 256;
            int r = idx >> 3;
            int q = idx & 7;
            uint32_t so = (uint32_t)((r * ROWF + q * 4) * 4);
            cp16(aoff + so, Abase + (long)r * GK + kc * BKC + q * 4);
            cp16(woff + so, Wbase + (long)r * GK + kc * BKC + q * 4);
        }
    };

    float acc[4][4][4];
#pragma unroll
    for (int mi = 0; mi < 4; mi++)
#pragma unroll
        for (int ni = 0; ni < 4; ni++)
#pragma unroll
            for (int r = 0; r < 4; r++) acc[mi][ni][r] = 0.f;

    load_chunk(0, 0); CP_COMMIT();
    load_chunk(1, 1); CP_COMMIT();

    const int NCH = GK / BKC;
    for (int k0 = 0; k0 < NCH; k0++) {
        const int buf = k0 & 1;
        if (k0 + 1 < NCH) { CP_WAIT(1); } else { CP_WAIT(0); }
        __syncthreads();

        const float* As = sA[buf];
        const float* Ws = sW[buf];
#pragma unroll
        for (int kk = 0; kk < 4; kk++) {
            const int k8 = kk * 8;
            uint32_t bh[4][2], bl[4][2];
#pragma unroll
            for (int ni = 0; ni < 4; ni++) {
                const int r0 = nbase + ni * 8 + g;
                tf32_split(Ws[r0 * ROWF + k8 + tig],     bh[ni][0], bl[ni][0]);
                tf32_split(Ws[r0 * ROWF + k8 + tig + 4], bh[ni][1], bl[ni][1]);
            }
#pragma unroll
            for (int mi = 0; mi < 4; mi++) {
                const int r0 = mbase + mi * 16 + g;
                uint32_t ah[4], al[4];
                tf32_split(As[r0 * ROWF + k8 + tig],           ah[0], al[0]);
                tf32_split(As[(r0 + 8) * ROWF + k8 + tig],     ah[1], al[1]);
                tf32_split(As[r0 * ROWF + k8 + tig + 4],       ah[2], al[2]);
                tf32_split(As[(r0 + 8) * ROWF + k8 + tig + 4], ah[3], al[3]);
#pragma unroll
                for (int ni = 0; ni < 4; ni++) {
                    mma_tf32(acc[mi][ni], ah, bh[ni]);
                    mma_tf32(acc[mi][ni], ah, bl[ni]);
                    mma_tf32(acc[mi][ni], al, bh[ni]);
                }
            }
        }
        __syncthreads();
        if (k0 + 2 < NCH) { load_chunk(k0 + 2, buf); CP_COMMIT(); }
    }

#pragma unroll
    for (int ni = 0; ni < 4; ni++) {
        const int gcol = bx * 128 + nbase + ni * 8 + 2 * tig;
        const float b0 = bias[gcol];
        const float b1 = bias[gcol + 1];
        const int which = gcol >> 10;
        const int hh = (gcol >> 6) & 15;
        const int dd = gcol & 63;
        float* dst = (MODE == 0)
                   ? ((which == 0) ? g_q : ((which == 1) ? g_k : g_v))
                   : C;
#pragma unroll
        for (int mi = 0; mi < 4; mi++) {
#pragma unroll
            for (int h = 0; h < 2; h++) {
                const int rr = by * 128 + mbase + mi * 16 + g + h * 8;
                float2 o;
                o.x = acc[mi][ni][2 * h + 0] + b0;
                o.y = acc[mi][ni][2 * h + 1] + b1;
                if (MODE == 0) {
                    const int bb = rr >> 10, ss = rr & 1023;
                    *(float2*)(dst + ((long)(bb * HN + hh) * SQ + ss) * AD + dd) = o;
                } else {
                    *(float2*)(dst + (long)rr * N + gcol) = o;
                }
            }
        }
    }
}

// ===========================================================================
// Tensor-core attention with SparseNormer (3xTF32 mma.sync)
// Grid (8,16,4), 256 threads = 8 warps; q tile = 128 rows; warp w owns rows
// [16w,16w+16). k/v tiles [64x64] cp.async double-buffered.
//   S = q k^T (3xTF32) -> +rel, *0.125, +bias, relu^2 -> t (via smem relayout)
//   O += t V (3xTF32); den accumulated per-thread, shfl-reduced over tig lanes
//   ctx = O / (den + eps)
// ===========================================================================
#define AQT  128
#define AST  68                            // smem row stride (68*4=272B, 16B-aligned)
#define A_Q    0                           // [128][AST]
#define A_KV   (A_Q + 128*AST)             // k0,v0,k1,v1 each [64][AST]
#define A_TST  (A_KV + 4*64*AST)           // [128][AST]  (preamble: rels [33][AST])
#define A_RQS  (A_TST + 128*AST)           // [128][36]
#define A_TOTF (A_RQS + 128*36)
#define A_BYTES (A_TOTF*4)

__global__ __launch_bounds__(256, 1)
void attn_mma(const float* __restrict__ rel_emb, const float* __restrict__ snb_p)
{
    extern __shared__ __align__(16) float sm[];
    const int tid  = threadIdx.x;
    const int wid  = tid >> 5;
    const int lane = tid & 31;
    const int g    = lane >> 2;
    const int tig  = lane & 3;
    const int qt = blockIdx.x, h = blockIdx.y, b = blockIdx.z;
    const int bh = b * HN + h;
    const int q0 = qt * AQT;
    const int mb = wid * 16;
    const float snb = __ldg(snb_p);

    const float* Qg = g_q + ((long)bh * SQ + q0) * AD;
    const float* Kg = g_k + (long)bh * SQ * AD;
    const float* Vg = g_v + (long)bh * SQ * AD;

    const uint32_t sb  = smem_u32(sm);
    const uint32_t sQ  = sb + A_Q * 4;
    const uint32_t sKV = sb + A_KV * 4;
    const uint32_t sT  = sb + A_TST * 4;

    // q tile [128][64] -> [r][d] row-major (2048 float4)
#pragma unroll
    for (int i = 0; i < 8; i++) {
        int idx = tid + i * 256;
        int r = idx >> 4, c = idx & 15;
        cp16(sQ + (uint32_t)(r * AST + c * 4) * 4, Qg + r * AD + c * 4);
    }
    // rel_emb [33][64] into tst area (alias; freed after rqs)
    for (int i = tid; i < 33 * 16; i += 256) {
        int r = i >> 4, c = i & 15;
        cp16(sT + (uint32_t)(r * AST + c * 4) * 4, rel_emb + r * 64 + c * 4);
    }
    CP_COMMIT();

    auto load_kv = [&](int kt, int buf) {
        const float* Kt = Kg + (long)kt * 64 * AD;
        const float* Vt = Vg + (long)kt * 64 * AD;
        uint32_t kb = sKV + (uint32_t)(buf * 2 * 64 * AST) * 4;
        uint32_t vb = kb + (uint32_t)(64 * AST) * 4;
#pragma unroll
        for (int i = 0; i < 4; i++) {
            int idx = tid + i * 256;
            int r = idx >> 4, c = idx & 15;
            uint32_t so = (uint32_t)(r * AST + c * 4) * 4;
            cp16(kb + so, Kt + r * AD + c * 4);
            cp16(vb + so, Vt + r * AD + c * 4);
        }
    };
    load_kv(0, 0); CP_COMMIT();
    load_kv(1, 1); CP_COMMIT();

    CP_WAIT(2);                 // q + rels landed
    __syncthreads();

    // rq[r][p] = q_r . rel_emb[p]
    float* qf   = sm + A_Q;
    float* relf = sm + A_TST;
    float* rqs  = sm + A_RQS;
    for (int i = tid; i < 128 * 33; i += 256) {
        int r = i / 33, p = i - r * 33;
        float s = 0.f;
#pragma unroll 16
        for (int d = 0; d < 64; d++) s = fmaf(qf[r * AST + d], relf[p * AST + d], s);
        rqs[r * 36 + p] = s;
    }
    __syncthreads();            // rqs ready; tst area now free

    float oacc[8][4];
#pragma unroll
    for (int ni = 0; ni < 8; ni++)
#pragma unroll
        for (int r = 0; r < 4; r++) oacc[ni][r] = 0.f;
    float denp0 = 0.f, denp1 = 0.f;

    float* tstf = sm + A_TST;
    const int ig0 = q0 + mb + g;

    for (int kt = 0; kt < 16; kt++) {
        const int buf = kt & 1;
        if (kt + 1 < 16) { CP_WAIT(1); } else { CP_WAIT(0); }
        __syncthreads();
        const float* kb = sm + A_KV + buf * 2 * 64 * AST;
        const float* vb = kb + 64 * AST;

        // --- S = q k^T (3xTF32), c-frags sacc[ni] cover cols ni*8 .. ni*8+7
        float sacc[8][4];
#pragma unroll
        for (int ni = 0; ni < 8; ni++)
#pragma unroll
            for (int r = 0; r < 4; r++) sacc[ni][r] = 0.f;
#pragma unroll
        for (int kk = 0; kk < 8; kk++) {
            const int k8 = kk * 8;
            uint32_t ah[4], al[4];
            tf32_split(qf[(mb + g) * AST + k8 + tig],         ah[0], al[0]);
            tf32_split(qf[(mb + g + 8) * AST + k8 + tig],     ah[1], al[1]);
            tf32_split(qf[(mb + g) * AST + k8 + tig + 4],     ah[2], al[2]);
            tf32_split(qf[(mb + g + 8) * AST + k8 + tig + 4], ah[3], al[3]);
#pragma unroll
            for (int ni = 0; ni < 8; ni++) {
                uint32_t bh2[2], bl2[2];
                tf32_split(kb[(ni * 8 + g) * AST + k8 + tig],     bh2[0], bl2[0]);
                tf32_split(kb[(ni * 8 + g) * AST + k8 + tig + 4], bh2[1], bl2[1]);
                mma_tf32(sacc[ni], ah, bh2);
                mma_tf32(sacc[ni], ah, bl2);
                mma_tf32(sacc[ni], al, bh2);
            }
        }

        // --- elementwise: t = relu((S + rel)/8 + b)^2 ; stage into tst (own rows)
#pragma unroll
        for (int ni = 0; ni < 8; ni++) {
            const int cbase = ni * 8 + 2 * tig;
            const int jbase = kt * 64 + cbase;
            float t0, t1;
            {   // row g
                int d0 = jbase - ig0;     d0 = (d0 < -KREL) ? -KREL : ((d0 > KREL) ? KREL : d0);
                int d1 = jbase + 1 - ig0; d1 = (d1 < -KREL) ? -KREL : ((d1 > KREL) ? KREL : d1);
                float s0 = (sacc[ni][0] + rqs[(mb + g) * 36 + d0 + KREL]) * 0.125f + snb;
                float s1 = (sacc[ni][1] + rqs[(mb + g) * 36 + d1 + KREL]) * 0.125f + snb;
                s0 = fmaxf(s0, 0.f); s1 = fmaxf(s1, 0.f);
                t0 = s0 * s0; t1 = s1 * s1;
            }
            denp0 += t0 + t1;
            *(float2*)&tstf[(mb + g) * AST + cbase] = make_float2(t0, t1);
            {   // row g+8
                int d0 = jbase - (ig0 + 8);     d0 = (d0 < -KREL) ? -KREL : ((d0 > KREL) ? KREL : d0);
                int d1 = jbase + 1 - (ig0 + 8); d1 = (d1 < -KREL) ? -KREL : ((d1 > KREL) ? KREL : d1);
                float s0 = (sacc[ni][2] + rqs[(mb + g + 8) * 36 + d0 + KREL]) * 0.125f + snb;
                float s1 = (sacc[ni][3] + rqs[(mb + g + 8) * 36 + d1 + KREL]) * 0.125f + snb;
                s0 = fmaxf(s0, 0.f); s1 = fmaxf(s1, 0.f);
                t0 = s0 * s0; t1 = s1 * s1;
            }
            denp1 += t0 + t1;
            *(float2*)&tstf[(mb + g + 8) * AST + cbase] = make_float2(t0, t1);
        }
        __syncwarp();           // own-rows handoff: warp-local only

        // --- O += t V (3xTF32); oacc[ni] cover dims ni*8 .. ni*8+7
#pragma unroll
        for (int kk = 0; kk < 8; kk++) {
            const int k8 = kk * 8;
            uint32_t ah[4], al[4];
            tf32_split(tstf[(mb + g) * AST + k8 + tig],         ah[0], al[0]);
            tf32_split(tstf[(mb + g + 8) * AST + k8 + tig],     ah[1], al[1]);
            tf32_split(tstf[(mb + g) * AST + k8 + tig + 4],     ah[2], al[2]);
            tf32_split(tstf[(mb + g + 8) * AST + k8 + tig + 4], ah[3], al[3]);
#pragma unroll
            for (int ni = 0; ni < 8; ni++) {
                uint32_t bh2[2], bl2[2];
                tf32_split(vb[(k8 + tig) * AST + ni * 8 + g],     bh2[0], bl2[0]);
                tf32_split(vb[(k8 + tig + 4) * AST + ni * 8 + g], bh2[1], bl2[1]);
                mma_tf32(oacc[ni], ah, bh2);
                mma_tf32(oacc[ni], ah, bl2);
                mma_tf32(oacc[ni], al, bh2);
            }
        }
        __syncthreads();        // all warps done with kv[buf] before refill
        if (kt + 2 < 16) { load_kv(kt + 2, buf); CP_COMMIT(); }
    }

    // deterministic den reduction across the 4 tig lanes of each g-quad
    denp0 += __shfl_xor_sync(0xffffffffu, denp0, 1);
    denp0 += __shfl_xor_sync(0xffffffffu, denp0, 2);
    denp1 += __shfl_xor_sync(0xffffffffu, denp1, 1);
    denp1 += __shfl_xor_sync(0xffffffffu, denp1, 2);
    const float inv0 = 1.f / (denp0 + SN_EPS);
    const float inv1 = 1.f / (denp1 + SN_EPS);

    float* ctx0 = g_ctx + (long)(b * SQ + q0 + mb + g) * DM + h * AD;
    float* ctx8 = ctx0 + 8 * DM;
#pragma unroll
    for (int ni = 0; ni < 8; ni++) {
        const int c = ni * 8 + 2 * tig;
        *(float2*)(ctx0 + c) = make_float2(oacc[ni][0] * inv0, oacc[ni][1] * inv0);
        *(float2*)(ctx8 + c) = make_float2(oacc[ni][2] * inv1, oacc[ni][3] * inv1);
    }
}

// ===========================================================================
extern "C" void kernel_launch(void* const* d_in, const int* in_sizes, int n_in,
                              void* d_out, int out_size)
{
    (void)in_sizes; (void)n_in; (void)out_size;
    const float* iQ  = (const float*)d_in[0];
    const float* Wa  = (const float*)d_in[1];
    const float* ba  = (const float*)d_in[2];
    const float* rel = (const float*)d_in[3];
    const float* snb = (const float*)d_in[4];
    const float* Wo  = (const float*)d_in[5];
    const float* bo  = (const float*)d_in[6];
    float* out = (float*)d_out;

    cudaFuncSetAttribute(tc_gemm<0>, cudaFuncAttributeMaxDynamicSharedMemorySize, GSM_BYTES);
    cudaFuncSetAttribute(tc_gemm<1>, cudaFuncAttributeMaxDynamicSharedMemorySize, GSM_BYTES);
    cudaFuncSetAttribute(attn_mma,   cudaFuncAttributeMaxDynamicSharedMemorySize, A_BYTES);

    // 1) QKV projection (3xTF32 mma.sync)
    tc_gemm<0><<<dim3(3072 / 128, 4096 / 128), 256, GSM_BYTES>>>(iQ, Wa, ba, nullptr, 3072);

    // 2) tensor-core relative-position attention + SparseNormer -> g_ctx
    attn_mma<<<dim3(SQ / AQT, HN, NB), 256, A_BYTES>>>(rel, snb);

    // 3) output projection (3xTF32 mma.sync)
    tc_gemm<1><<<dim3(1024 / 128, 4096 / 128), 256, GSM_BYTES>>>(nullptr, Wo, bo, out, 1024);
}

// round 12
// speedup vs baseline: 2.1783x; 1.4322x over previous
#include <cuda_runtime.h>
#include <cstdint>

// Problem constants
#define HN    16
#define AD    64
#define SQ    1024
#define NB    4
#define DM    1024
#define KREL  16
#define SN_EPS 1e-8f

// Scratch (device globals: no runtime allocation allowed)
__device__ __align__(16) float g_q[NB * HN * SQ * AD];     // [B,H,S,AD]
__device__ __align__(16) float g_k[NB * HN * SQ * AD];
__device__ __align__(16) float g_v[NB * HN * SQ * AD];
__device__ __align__(16) float g_ctx[NB * SQ * DM];        // [B,S,H*AD]

// ===========================================================================
// Helpers (baseline sm_80+ PTX only)
// ===========================================================================
__device__ __forceinline__ void cp16(uint32_t saddr, const void* g) {
    asm volatile("cp.async.cg.shared.global [%0], [%1], 16;\n" :: "r"(saddr), "l"(g));
}
#define CP_COMMIT() asm volatile("cp.async.commit_group;\n" ::: "memory")
#define CP_WAIT(n)  asm volatile("cp.async.wait_group %0;\n" :: "n"(n) : "memory")

__device__ __forceinline__ uint32_t smem_u32(const void* p) {
    uint32_t a;
    asm("{ .reg .u64 t; cvta.to.shared.u64 t, %1; cvt.u32.u64 %0, t; }"
        : "=r"(a) : "l"(p));
    return a;
}

// mma.sync m16n8k16 bf16: A=4 regs (bf16x2), B=2 regs, C=4 fp32
__device__ __forceinline__ void mma_bf16(float c[4], const uint32_t a[4], const uint32_t b[2]) {
    asm volatile(
        "mma.sync.aligned.m16n8k16.row.col.f32.bf16.bf16.f32 "
        "{%0,%1,%2,%3}, {%4,%5,%6,%7}, {%8,%9}, {%0,%1,%2,%3};"
        : "+f"(c[0]), "+f"(c[1]), "+f"(c[2]), "+f"(c[3])
        : "r"(a[0]), "r"(a[1]), "r"(a[2]), "r"(a[3]), "r"(b[0]), "r"(b[1]));
}

// From two adjacent fp32 values produce packed bf16x2 hi and lo parts:
//   hi_i = x_i truncated to bf16 (exact),  lo_i = x_i - hi_i  (exact fp32,
//   |lo| <= 2^-8 |x|), lo packed by truncation (residual <= 2^-16 |x|).
__device__ __forceinline__ void bsplit(float x0, float x1, uint32_t& hi, uint32_t& lo) {
    uint32_t h0 = __float_as_uint(x0) & 0xFFFF0000u;
    uint32_t h1 = __float_as_uint(x1) & 0xFFFF0000u;
    hi = __byte_perm(h0, h1, 0x7632);
    float l0 = x0 - __uint_as_float(h0);
    float l1 = x1 - __uint_as_float(h1);
    lo = __byte_perm(__float_as_uint(l0), __float_as_uint(l1), 0x7632);
}

// ===========================================================================
// 3xBF16 mma.sync GEMM:  C[m,n] = sum_k A[m,k] * W[n,k] + bias[n]
// BM=BN=128, BK=32, 256 threads (8 warps 2x4), warp tile 64x32,
// 4x4 m16n8k16 fragments, each as Ah*Bh + Ah*Bl + Al*Bh (residual ~2^-16).
// cp.async double buffer; ROWF=40 pad -> conflict-free float2 fragment LDS.
// MODE 0: QKV projection (A = iQ), scatter into g_q/g_k/g_v
// MODE 1: output projection (A = g_ctx), dense row-major C
// ===========================================================================
#define GK      1024
#define BKC     32
#define ROWF    40
#define TILE_F  (128 * ROWF)
#define GSM_FLOATS (4 * TILE_F)
#define GSM_BYTES  (GSM_FLOATS * 4)

template <int MODE>
__global__ __launch_bounds__(256, 2)
void tc_gemm(const float* __restrict__ A_in, const float* __restrict__ W,
             const float* __restrict__ bias, float* __restrict__ C, int N)
{
    extern __shared__ __align__(16) float smem[];
    float* sA[2] = { smem,              smem + 2 * TILE_F };
    float* sW[2] = { smem + TILE_F,     smem + 3 * TILE_F };

    const int tid  = threadIdx.x;
    const int wid  = tid >> 5;
    const int lane = tid & 31;
    const int g    = lane >> 2;
    const int tig  = lane & 3;
    const int wm   = wid >> 2;
    const int wn   = wid & 3;
    const int mbase = wm * 64;
    const int nbase = wn * 32;

    const int bx = blockIdx.x;
    const int by = blockIdx.y;

    const float* A = (MODE == 1) ? (const float*)g_ctx : A_in;
    const float* Abase = A + (long)(by * 128) * GK;
    const float* Wbase = W + (long)(bx * 128) * GK;

    const uint32_t sbase = smem_u32(smem);
    auto load_chunk = [&](int kc, int buf) {
        const uint32_t aoff = sbase + (uint32_t)((buf ? 2 * TILE_F : 0) * 4);
        const uint32_t woff = sbase + (uint32_t)(((buf ? 3 * TILE_F : TILE_F)) * 4);
#pragma unroll
        for (int i = 0; i < 4; i++) {
            int idx = tid + i * 256;
            int r = idx >> 3;
            int q = idx & 7;
            uint32_t so = (uint32_t)((r * ROWF + q * 4) * 4);
            cp16(aoff + so, Abase + (long)r * GK + kc * BKC + q * 4);
            cp16(woff + so, Wbase + (long)r * GK + kc * BKC + q * 4);
        }
    };

    float acc[4][4][4];
#pragma unroll
    for (int mi = 0; mi < 4; mi++)
#pragma unroll
        for (int ni = 0; ni < 4; ni++)
#pragma unroll
            for (int r = 0; r < 4; r++) acc[mi][ni][r] = 0.f;

    load_chunk(0, 0); CP_COMMIT();
    load_chunk(1, 1); CP_COMMIT();

    const int NCH = GK / BKC;
    for (int k0 = 0; k0 < NCH; k0++) {
        const int buf = k0 & 1;
        if (k0 + 1 < NCH) { CP_WAIT(1); } else { CP_WAIT(0); }
        __syncthreads();

        const float* As = sA[buf];
        const float* Ws = sW[buf];
#pragma unroll
        for (int kk = 0; kk < 2; kk++) {
            const int k16 = kk * 16;
            uint32_t bh[4][2], bl[4][2];
#pragma unroll
            for (int ni = 0; ni < 4; ni++) {
                const int r0 = nbase + ni * 8 + g;
                float2 w0 = *(const float2*)&Ws[r0 * ROWF + k16 + 2 * tig];
                float2 w1 = *(const float2*)&Ws[r0 * ROWF + k16 + 2 * tig + 8];
                bsplit(w0.x, w0.y, bh[ni][0], bl[ni][0]);
                bsplit(w1.x, w1.y, bh[ni][1], bl[ni][1]);
            }
#pragma unroll
            for (int mi = 0; mi < 4; mi++) {
                const int r0 = mbase + mi * 16 + g;
                uint32_t ah[4], al[4];
                float2 a0 = *(const float2*)&As[r0 * ROWF + k16 + 2 * tig];
                float2 a1 = *(const float2*)&As[(r0 + 8) * ROWF + k16 + 2 * tig];
                float2 a2 = *(const float2*)&As[r0 * ROWF + k16 + 2 * tig + 8];
                float2 a3 = *(const float2*)&As[(r0 + 8) * ROWF + k16 + 2 * tig + 8];
                bsplit(a0.x, a0.y, ah[0], al[0]);
                bsplit(a1.x, a1.y, ah[1], al[1]);
                bsplit(a2.x, a2.y, ah[2], al[2]);
                bsplit(a3.x, a3.y, ah[3], al[3]);
#pragma unroll
                for (int ni = 0; ni < 4; ni++) {
                    mma_bf16(acc[mi][ni], ah, bh[ni]);
                    mma_bf16(acc[mi][ni], ah, bl[ni]);
                    mma_bf16(acc[mi][ni], al, bh[ni]);
                }
            }
        }
        __syncthreads();
        if (k0 + 2 < NCH) { load_chunk(k0 + 2, buf); CP_COMMIT(); }
    }

#pragma unroll
    for (int ni = 0; ni < 4; ni++) {
        const int gcol = bx * 128 + nbase + ni * 8 + 2 * tig;
        const float b0 = bias[gcol];
        const float b1 = bias[gcol + 1];
        const int which = gcol >> 10;
        const int hh = (gcol >> 6) & 15;
        const int dd = gcol & 63;
        float* dst = (MODE == 0)
                   ? ((which == 0) ? g_q : ((which == 1) ? g_k : g_v))
                   : C;
#pragma unroll
        for (int mi = 0; mi < 4; mi++) {
#pragma unroll
            for (int h = 0; h < 2; h++) {
                const int rr = by * 128 + mbase + mi * 16 + g + h * 8;
                float2 o;
                o.x = acc[mi][ni][2 * h + 0] + b0;
                o.y = acc[mi][ni][2 * h + 1] + b1;
                if (MODE == 0) {
                    const int bb = rr >> 10, ss = rr & 1023;
                    *(float2*)(dst + ((long)(bb * HN + hh) * SQ + ss) * AD + dd) = o;
                } else {
                    *(float2*)(dst + (long)rr * N + gcol) = o;
                }
            }
        }
    }
}

// ===========================================================================
// Tensor-core attention with SparseNormer (3xBF16 mma.sync)
// Grid (8,16,4), 256 threads = 8 warps; q tile 128 rows; warp w owns rows
// [16w,16w+16). k/v tiles [64x64] cp.async double-buffered.
// ===========================================================================
#define AQT  128
#define AST  72                            // row stride: (8g+2tig)%32 conflict-free
#define A_Q    0                           // [128][AST]
#define A_KV   (A_Q + 128*AST)             // k0,v0,k1,v1 each [64][AST]
#define A_TST  (A_KV + 4*64*AST)           // [128][AST]  (preamble: rels [33][AST])
#define A_RQS  (A_TST + 128*AST)           // [128][36]
#define A_TOTF (A_RQS + 128*36)
#define A_BYTES (A_TOTF*4)

__global__ __launch_bounds__(256, 1)
void attn_mma(const float* __restrict__ rel_emb, const float* __restrict__ snb_p)
{
    extern __shared__ __align__(16) float sm[];
    const int tid  = threadIdx.x;
    const int wid  = tid >> 5;
    const int lane = tid & 31;
    const int g    = lane >> 2;
    const int tig  = lane & 3;
    const int qt = blockIdx.x, h = blockIdx.y, b = blockIdx.z;
    const int bh = b * HN + h;
    const int q0 = qt * AQT;
    const int mb = wid * 16;
    const float snb = __ldg(snb_p);

    const float* Qg = g_q + ((long)bh * SQ + q0) * AD;
    const float* Kg = g_k + (long)bh * SQ * AD;
    const float* Vg = g_v + (long)bh * SQ * AD;

    const uint32_t sb  = smem_u32(sm);
    const uint32_t sQ  = sb + A_Q * 4;
    const uint32_t sKV = sb + A_KV * 4;
    const uint32_t sT  = sb + A_TST * 4;

    // q tile [128][64]
#pragma unroll
    for (int i = 0; i < 8; i++) {
        int idx = tid + i * 256;
        int r = idx >> 4, c = idx & 15;
        cp16(sQ + (uint32_t)(r * AST + c * 4) * 4, Qg + r * AD + c * 4);
    }
    // rel_emb [33][64] into tst area (alias; freed after rqs)
    for (int i = tid; i < 33 * 16; i += 256) {
        int r = i >> 4, c = i & 15;
        cp16(sT + (uint32_t)(r * AST + c * 4) * 4, rel_emb + r * 64 + c * 4);
    }
    CP_COMMIT();

    auto load_kv = [&](int kt, int buf) {
        const float* Kt = Kg + (long)kt * 64 * AD;
        const float* Vt = Vg + (long)kt * 64 * AD;
        uint32_t kb = sKV + (uint32_t)(buf * 2 * 64 * AST) * 4;
        uint32_t vb = kb + (uint32_t)(64 * AST) * 4;
#pragma unroll
        for (int i = 0; i < 4; i++) {
            int idx = tid + i * 256;
            int r = idx >> 4, c = idx & 15;
            uint32_t so = (uint32_t)(r * AST + c * 4) * 4;
            cp16(kb + so, Kt + r * AD + c * 4);
            cp16(vb + so, Vt + r * AD + c * 4);
        }
    };
    load_kv(0, 0); CP_COMMIT();
    load_kv(1, 1); CP_COMMIT();

    CP_WAIT(2);                 // q + rels landed
    __syncthreads();

    // rq[r][p] = q_r . rel_emb[p]
    float* qf   = sm + A_Q;
    float* relf = sm + A_TST;
    float* rqs  = sm + A_RQS;
    for (int i = tid; i < 128 * 33; i += 256) {
        int r = i / 33, p = i - r * 33;
        float s = 0.f;
#pragma unroll 16
        for (int d = 0; d < 64; d++) s = fmaf(qf[r * AST + d], relf[p * AST + d], s);
        rqs[r * 36 + p] = s;
    }
    __syncthreads();            // rqs ready; tst area now free

    float oacc[8][4];
#pragma unroll
    for (int ni = 0; ni < 8; ni++)
#pragma unroll
        for (int r = 0; r < 4; r++) oacc[ni][r] = 0.f;
    float denp0 = 0.f, denp1 = 0.f;

    float* tstf = sm + A_TST;
    const int ig0 = q0 + mb + g;

    for (int kt = 0; kt < 16; kt++) {
        const int buf = kt & 1;
        if (kt + 1 < 16) { CP_WAIT(1); } else { CP_WAIT(0); }
        __syncthreads();
        const float* kb = sm + A_KV + buf * 2 * 64 * AST;
        const float* vb = kb + 64 * AST;

        // --- S = q k^T (3xBF16); sacc[ni] covers cols ni*8 .. ni*8+7
        float sacc[8][4];
#pragma unroll
        for (int ni = 0; ni < 8; ni++)
#pragma unroll
            for (int r = 0; r < 4; r++) sacc[ni][r] = 0.f;
#pragma unroll
        for (int kk = 0; kk < 4; kk++) {
            const int k16 = kk * 16;
            uint32_t ah[4], al[4];
            float2 a0 = *(const float2*)&qf[(mb + g) * AST + k16 + 2 * tig];
            float2 a1 = *(const float2*)&qf[(mb + g + 8) * AST + k16 + 2 * tig];
            float2 a2 = *(const float2*)&qf[(mb + g) * AST + k16 + 2 * tig + 8];
            float2 a3 = *(const float2*)&qf[(mb + g + 8) * AST + k16 + 2 * tig + 8];
            bsplit(a0.x, a0.y, ah[0], al[0]);
            bsplit(a1.x, a1.y, ah[1], al[1]);
            bsplit(a2.x, a2.y, ah[2], al[2]);
            bsplit(a3.x, a3.y, ah[3], al[3]);
#pragma unroll
            for (int ni = 0; ni < 8; ni++) {
                uint32_t bh2[2], bl2[2];
                float2 w0 = *(const float2*)&kb[(ni * 8 + g) * AST + k16 + 2 * tig];
                float2 w1 = *(const float2*)&kb[(ni * 8 + g) * AST + k16 + 2 * tig + 8];
                bsplit(w0.x, w0.y, bh2[0], bl2[0]);
                bsplit(w1.x, w1.y, bh2[1], bl2[1]);
                mma_bf16(sacc[ni], ah, bh2);
                mma_bf16(sacc[ni], ah, bl2);
                mma_bf16(sacc[ni], al, bh2);
            }
        }

        // --- elementwise: t = relu((S + rel)/8 + b)^2 ; stage into tst (own rows)
#pragma unroll
        for (int ni = 0; ni < 8; ni++) {
            const int cbase = ni * 8 + 2 * tig;
            const int jbase = kt * 64 + cbase;
            float t0, t1;
            {   // row g
                int d0 = jbase - ig0;     d0 = (d0 < -KREL) ? -KREL : ((d0 > KREL) ? KREL : d0);
                int d1 = jbase + 1 - ig0; d1 = (d1 < -KREL) ? -KREL : ((d1 > KREL) ? KREL : d1);
                float s0 = (sacc[ni][0] + rqs[(mb + g) * 36 + d0 + KREL]) * 0.125f + snb;
                float s1 = (sacc[ni][1] + rqs[(mb + g) * 36 + d1 + KREL]) * 0.125f + snb;
                s0 = fmaxf(s0, 0.f); s1 = fmaxf(s1, 0.f);
                t0 = s0 * s0; t1 = s1 * s1;
            }
            denp0 += t0 + t1;
            *(float2*)&tstf[(mb + g) * AST + cbase] = make_float2(t0, t1);
            {   // row g+8
                int d0 = jbase - (ig0 + 8);     d0 = (d0 < -KREL) ? -KREL : ((d0 > KREL) ? KREL : d0);
                int d1 = jbase + 1 - (ig0 + 8); d1 = (d1 < -KREL) ? -KREL : ((d1 > KREL) ? KREL : d1);
                float s0 = (sacc[ni][2] + rqs[(mb + g + 8) * 36 + d0 + KREL]) * 0.125f + snb;
                float s1 = (sacc[ni][3] + rqs[(mb + g + 8) * 36 + d1 + KREL]) * 0.125f + snb;
                s0 = fmaxf(s0, 0.f); s1 = fmaxf(s1, 0.f);
                t0 = s0 * s0; t1 = s1 * s1;
            }
            denp1 += t0 + t1;
            *(float2*)&tstf[(mb + g + 8) * AST + cbase] = make_float2(t0, t1);
        }
        __syncwarp();           // own-rows handoff: warp-local only

        // --- O += t V (3xBF16); oacc[ni] covers dims ni*8 .. ni*8+7
#pragma unroll
        for (int kk = 0; kk < 4; kk++) {
            const int k16 = kk * 16;
            uint32_t ah[4], al[4];
            float2 a0 = *(const float2*)&tstf[(mb + g) * AST + k16 + 2 * tig];
            float2 a1 = *(const float2*)&tstf[(mb + g + 8) * AST + k16 + 2 * tig];
            float2 a2 = *(const float2*)&tstf[(mb + g) * AST + k16 + 2 * tig + 8];
            float2 a3 = *(const float2*)&tstf[(mb + g + 8) * AST + k16 + 2 * tig + 8];
            bsplit(a0.x, a0.y, ah[0], al[0]);
            bsplit(a1.x, a1.y, ah[1], al[1]);
            bsplit(a2.x, a2.y, ah[2], al[2]);
            bsplit(a3.x, a3.y, ah[3], al[3]);
#pragma unroll
            for (int ni = 0; ni < 8; ni++) {
                uint32_t bh2[2], bl2[2];
                // B element (n, k) = v[k][n]; k pairs non-adjacent (row stride)
                float v00 = vb[(k16 + 2 * tig) * AST + ni * 8 + g];
                float v01 = vb[(k16 + 2 * tig + 1) * AST + ni * 8 + g];
                bsplit(v00, v01, bh2[0], bl2[0]);
                float v10 = vb[(k16 + 2 * tig + 8) * AST + ni * 8 + g];
                float v11 = vb[(k16 + 2 * tig + 9) * AST + ni * 8 + g];
                bsplit(v10, v11, bh2[1], bl2[1]);
                mma_bf16(oacc[ni], ah, bh2);
                mma_bf16(oacc[ni], ah, bl2);
                mma_bf16(oacc[ni], al, bh2);
            }
        }
        __syncthreads();        // all warps done with kv[buf] before refill
        if (kt + 2 < 16) { load_kv(kt + 2, buf); CP_COMMIT(); }
    }

    // deterministic den reduction across the 4 tig lanes of each g-quad
    denp0 += __shfl_xor_sync(0xffffffffu, denp0, 1);
    denp0 += __shfl_xor_sync(0xffffffffu, denp0, 2);
    denp1 += __shfl_xor_sync(0xffffffffu, denp1, 1);
    denp1 += __shfl_xor_sync(0xffffffffu, denp1, 2);
    const float inv0 = 1.f / (denp0 + SN_EPS);
    const float inv1 = 1.f / (denp1 + SN_EPS);

    float* ctx0 = g_ctx + (long)(b * SQ + q0 + mb + g) * DM + h * AD;
    float* ctx8 = ctx0 + 8 * DM;
#pragma unroll
    for (int ni = 0; ni < 8; ni++) {
        const int c = ni * 8 + 2 * tig;
        *(float2*)(ctx0 + c) = make_float2(oacc[ni][0] * inv0, oacc[ni][1] * inv0);
        *(float2*)(ctx8 + c) = make_float2(oacc[ni][2] * inv1, oacc[ni][3] * inv1);
    }
}

// ===========================================================================
extern "C" void kernel_launch(void* const* d_in, const int* in_sizes, int n_in,
                              void* d_out, int out_size)
{
    (void)in_sizes; (void)n_in; (void)out_size;
    const float* iQ  = (const float*)d_in[0];
    const float* Wa  = (const float*)d_in[1];
    const float* ba  = (const float*)d_in[2];
    const float* rel = (const float*)d_in[3];
    const float* snb = (const float*)d_in[4];
    const float* Wo  = (const float*)d_in[5];
    const float* bo  = (const float*)d_in[6];
    float* out = (float*)d_out;

    cudaFuncSetAttribute(tc_gemm<0>, cudaFuncAttributeMaxDynamicSharedMemorySize, GSM_BYTES);
    cudaFuncSetAttribute(tc_gemm<1>, cudaFuncAttributeMaxDynamicSharedMemorySize, GSM_BYTES);
    cudaFuncSetAttribute(attn_mma,   cudaFuncAttributeMaxDynamicSharedMemorySize, A_BYTES);

    // 1) QKV projection (3xBF16 mma.sync)
    tc_gemm<0><<<dim3(3072 / 128, 4096 / 128), 256, GSM_BYTES>>>(iQ, Wa, ba, nullptr, 3072);

    // 2) tensor-core relative-position attention + SparseNormer -> g_ctx
    attn_mma<<<dim3(SQ / AQT, HN, NB), 256, A_BYTES>>>(rel, snb);

    // 3) output projection (3xBF16 mma.sync)
    tc_gemm<1><<<dim3(1024 / 128, 4096 / 128), 256, GSM_BYTES>>>(nullptr, Wo, bo, out, 1024);
}

// round 13
// speedup vs baseline: 2.2518x; 1.0337x over previous
#include <cuda_runtime.h>
#include <cstdint>

// Problem constants
#define HN    16
#define AD    64
#define SQ    1024
#define NB    4
#define DM    1024
#define KREL  16
#define SN_EPS 1e-8f

// ---------------------------------------------------------------------------
// Scratch (device globals: no runtime allocation allowed).
// Packed bf16x2 convention: u32 = [bf16(x_even) low | bf16(x_odd) high],
// pairs along the K-contiguous dimension.
// ---------------------------------------------------------------------------
__device__ __align__(16) float    g_q   [NB * HN * SQ * AD];      // fp32 (rq needs it)
__device__ __align__(16) uint32_t g_k_h [NB * HN * SQ * AD / 2];  // [B,H,S,32] pairs along d
__device__ __align__(16) uint32_t g_k_l [NB * HN * SQ * AD / 2];
__device__ __align__(16) unsigned short g_vT_h[NB * HN * AD * SQ]; // [B,H,AD,S] transposed
__device__ __align__(16) unsigned short g_vT_l[NB * HN * AD * SQ];
__device__ __align__(16) uint32_t g_ctx_h[NB * SQ * DM / 2];      // [B,S,512]
__device__ __align__(16) uint32_t g_ctx_l[NB * SQ * DM / 2];
__device__ __align__(16) uint32_t g_iQ_h[4096 * 512];
__device__ __align__(16) uint32_t g_iQ_l[4096 * 512];
__device__ __align__(16) uint32_t g_Wa_h[3072 * 512];
__device__ __align__(16) uint32_t g_Wa_l[3072 * 512];
__device__ __align__(16) uint32_t g_Wo_h[1024 * 512];
__device__ __align__(16) uint32_t g_Wo_l[1024 * 512];

// ===========================================================================
// Helpers (baseline sm_80+ PTX only)
// ===========================================================================
__device__ __forceinline__ void cp16(uint32_t saddr, const void* g) {
    asm volatile("cp.async.cg.shared.global [%0], [%1], 16;\n" :: "r"(saddr), "l"(g));
}
#define CP_COMMIT() asm volatile("cp.async.commit_group;\n" ::: "memory")
#define CP_WAIT(n)  asm volatile("cp.async.wait_group %0;\n" :: "n"(n) : "memory")

__device__ __forceinline__ uint32_t smem_u32(const void* p) {
    uint32_t a;
    asm("{ .reg .u64 t; cvta.to.shared.u64 t, %1; cvt.u32.u64 %0, t; }"
        : "=r"(a) : "l"(p));
    return a;
}

__device__ __forceinline__ void mma_bf16(float c[4], const uint32_t a[4], const uint32_t b[2]) {
    asm volatile(
        "mma.sync.aligned.m16n8k16.row.col.f32.bf16.bf16.f32 "
        "{%0,%1,%2,%3}, {%4,%5,%6,%7}, {%8,%9}, {%0,%1,%2,%3};"
        : "+f"(c[0]), "+f"(c[1]), "+f"(c[2]), "+f"(c[3])
        : "r"(a[0]), "r"(a[1]), "r"(a[2]), "r"(a[3]), "r"(b[0]), "r"(b[1]));
}

// hi_i = bf16-truncate(x_i) (exact), lo_i = x_i - hi_i (|lo|<=2^-8|x|, bf16
// re-truncation residual <= 2^-16 |x|). Packed [x0 | x1].
__device__ __forceinline__ void bsplit(float x0, float x1, uint32_t& hi, uint32_t& lo) {
    uint32_t h0 = __float_as_uint(x0) & 0xFFFF0000u;
    uint32_t h1 = __float_as_uint(x1) & 0xFFFF0000u;
    hi = __byte_perm(h0, h1, 0x7632);
    float l0 = x0 - __uint_as_float(h0);
    float l1 = x1 - __uint_as_float(h1);
    lo = __byte_perm(__float_as_uint(l0), __float_as_uint(l1), 0x7632);
}

// ===========================================================================
// fp32 -> packed bf16x2 hi/lo converter (bandwidth-bound, grid-stride)
// ===========================================================================
__global__ void cvt_kernel(const float* __restrict__ src, uint32_t* __restrict__ h,
                           uint32_t* __restrict__ l, int npairs)
{
    for (int i = blockIdx.x * blockDim.x + threadIdx.x; i < npairs;
         i += gridDim.x * blockDim.x) {
        float2 v = ((const float2*)src)[i];
        uint32_t hi, lo;
        bsplit(v.x, v.y, hi, lo);
        h[i] = hi;
        l[i] = lo;
    }
}

// ===========================================================================
// 3xBF16 GEMM on PRE-SPLIT operands:  C[m,n] = sum_k A[m,k]*W[n,k] + bias[n]
// A,W given as packed hi/lo u32 arrays, [rows][512] (K=1024 floats).
// BM=BN=128, BK=32 floats (16 u32), 256 threads (8 warps 2x4), warp 64x32,
// 4x4 m16n8k16 frags, Ah*Bh + Ah*Bl + Al*Bh. NO splits in the hot loop.
// ROWU=20 u32 row pad -> bank (20g+tig)%32 conflict-free.
// MODE 0: QKV -> g_q fp32, g_k hi/lo, g_vT hi/lo (transposed bf16)
// MODE 1: out = ctx @ Wo^T + bo, fp32 row-major
// ===========================================================================
#define GKU    512
#define ROWU   20
#define TILEU  (128 * ROWU)
#define GSM_BYTES (2 * 4 * TILEU * 4)      // 2 buf x 4 tiles (Ah,Al,Wh,Wl)

template <int MODE>
__global__ __launch_bounds__(256, 2)
void tc_gemm(const uint32_t* __restrict__ Ahg, const uint32_t* __restrict__ Alg,
             const uint32_t* __restrict__ Whg, const uint32_t* __restrict__ Wlg,
             const float* __restrict__ bias, float* __restrict__ C, int N)
{
    extern __shared__ __align__(16) uint32_t smu[];

    const int tid  = threadIdx.x;
    const int wid  = tid >> 5;
    const int lane = tid & 31;
    const int g    = lane >> 2;
    const int tig  = lane & 3;
    const int wm   = wid >> 2;
    const int wn   = wid & 3;
    const int mbase = wm * 64;
    const int nbase = wn * 32;

    const int bx = blockIdx.x;
    const int by = blockIdx.y;

    const uint32_t* srcs[4] = {
        Ahg + (long)(by * 128) * GKU, Alg + (long)(by * 128) * GKU,
        Whg + (long)(bx * 128) * GKU, Wlg + (long)(bx * 128) * GKU };

    const uint32_t sbase = smem_u32(smu);
    auto load_chunk = [&](int kc, int buf) {
#pragma unroll
        for (int t = 0; t < 4; t++) {
#pragma unroll
            for (int i = 0; i < 2; i++) {
                int idx = tid + i * 256;          // 0..511
                int r = idx >> 2;                 // row 0..127
                int q = idx & 3;                  // u32 quad
                cp16(sbase + (uint32_t)(((buf * 4 + t) * TILEU + r * ROWU + q * 4) * 4),
                     srcs[t] + (long)r * GKU + kc * 16 + q * 4);
            }
        }
    };

    float acc[4][4][4];
#pragma unroll
    for (int mi = 0; mi < 4; mi++)
#pragma unroll
        for (int ni = 0; ni < 4; ni++)
#pragma unroll
            for (int r = 0; r < 4; r++) acc[mi][ni][r] = 0.f;

    load_chunk(0, 0); CP_COMMIT();
    load_chunk(1, 1); CP_COMMIT();

    const int NCH = 32;                    // 1024 / 32
    for (int k0 = 0; k0 < NCH; k0++) {
        const int buf = k0 & 1;
        if (k0 + 1 < NCH) { CP_WAIT(1); } else { CP_WAIT(0); }
        __syncthreads();

        const uint32_t* Ah = smu + (buf * 4 + 0) * TILEU;
        const uint32_t* Al = smu + (buf * 4 + 1) * TILEU;
        const uint32_t* Wh = smu + (buf * 4 + 2) * TILEU;
        const uint32_t* Wl = smu + (buf * 4 + 3) * TILEU;
#pragma unroll
        for (int kk = 0; kk < 2; kk++) {
            const int kc = kk * 8;
            uint32_t bh[4][2], bl[4][2];
#pragma unroll
            for (int ni = 0; ni < 4; ni++) {
                const int r0 = (nbase + ni * 8 + g) * ROWU + kc + tig;
                bh[ni][0] = Wh[r0];     bh[ni][1] = Wh[r0 + 4];
                bl[ni][0] = Wl[r0];     bl[ni][1] = Wl[r0 + 4];
            }
#pragma unroll
            for (int mi = 0; mi < 4; mi++) {
                const int r0 = (mbase + mi * 16 + g) * ROWU + kc + tig;
                const int r8 = r0 + 8 * ROWU;
                uint32_t ah[4], al[4];
                ah[0] = Ah[r0]; ah[1] = Ah[r8]; ah[2] = Ah[r0 + 4]; ah[3] = Ah[r8 + 4];
                al[0] = Al[r0]; al[1] = Al[r8]; al[2] = Al[r0 + 4]; al[3] = Al[r8 + 4];
#pragma unroll
                for (int ni = 0; ni < 4; ni++) {
                    mma_bf16(acc[mi][ni], ah, bh[ni]);
                    mma_bf16(acc[mi][ni], ah, bl[ni]);
                    mma_bf16(acc[mi][ni], al, bh[ni]);
                }
            }
        }
        __syncthreads();
        if (k0 + 2 < NCH) { load_chunk(k0 + 2, buf); CP_COMMIT(); }
    }

    // Epilogue: c-frag (m16n8) rows g,g+8; cols 2tig,2tig+1 (adjacent pair!)
#pragma unroll
    for (int ni = 0; ni < 4; ni++) {
        const int gcol = bx * 128 + nbase + ni * 8 + 2 * tig;
        const float b0 = bias[gcol];
        const float b1 = bias[gcol + 1];
        const int which = gcol >> 10;
        const int hh = (gcol >> 6) & 15;
        const int dd = gcol & 63;
#pragma unroll
        for (int mi = 0; mi < 4; mi++) {
#pragma unroll
            for (int h = 0; h < 2; h++) {
                const int rr = by * 128 + mbase + mi * 16 + g + h * 8;
                float2 o;
                o.x = acc[mi][ni][2 * h + 0] + b0;
                o.y = acc[mi][ni][2 * h + 1] + b1;
                if (MODE == 0) {
                    const int bb = rr >> 10, ss = rr & 1023;
                    const long bhq = (long)(bb * HN + hh);
                    if (which == 0) {
                        *(float2*)(g_q + (bhq * SQ + ss) * AD + dd) = o;
                    } else if (which == 1) {
                        uint32_t hi, lo;
                        bsplit(o.x, o.y, hi, lo);
                        const long idx = (bhq * SQ + ss) * 32 + (dd >> 1);
                        g_k_h[idx] = hi;
                        g_k_l[idx] = lo;
                    } else {
                        uint32_t hi, lo;
                        bsplit(o.x, o.y, hi, lo);
                        const long base = (bhq * AD + dd) * SQ + ss;
                        g_vT_h[base]      = (unsigned short)(hi & 0xFFFFu);
                        g_vT_h[base + SQ] = (unsigned short)(hi >> 16);
                        g_vT_l[base]      = (unsigned short)(lo & 0xFFFFu);
                        g_vT_l[base + SQ] = (unsigned short)(lo >> 16);
                    }
                } else {
                    *(float2*)(C + (long)rr * N + gcol) = o;
                }
            }
        }
    }
}

// ===========================================================================
// Tensor-core attention, pre-split bf16 operands. Grid (8,16,4), 256 thr.
// q tile 128 rows (warp w owns rows [16w,16w+16)); k/vT tiles [64x64] double-
// buffered. All hot-loop fragments are plain LDS.32 (no splits).
// ===========================================================================
// smem map in u32 units:
#define O_QH   0                           // [128][36] u32
#define O_QL   (O_QH + 128*36)
#define O_KV   (O_QL + 128*36)             // 2 buf x {KH,KL,VH,VL} x [64][36]
#define KVT    (64*36)
#define O_TH   (O_KV + 2*4*KVT)            // [128][36] u32   (preamble: q fp32)
#define O_TL   (O_TH + 128*36)
#define O_RELS (O_TL + 128*36)             // [33][68] fp32
#define O_RQS  (O_RELS + 33*68)            // [128][36] fp32
#define A_TOTU (O_RQS + 128*36)
#define A_BYTES (A_TOTU * 4)               // ~175 KB

__global__ __launch_bounds__(256, 1)
void attn_mma(const float* __restrict__ rel_emb, const float* __restrict__ snb_p)
{
    extern __shared__ __align__(16) uint32_t smu[];
    float* smf = (float*)smu;

    const int tid  = threadIdx.x;
    const int wid  = tid >> 5;
    const int lane = tid & 31;
    const int g    = lane >> 2;
    const int tig  = lane & 3;
    const int qt = blockIdx.x, h = blockIdx.y, b = blockIdx.z;
    const int bh = b * HN + h;
    const int q0 = qt * 128;
    const int mb = wid * 16;
    const float snb = __ldg(snb_p);

    const uint32_t sb = smem_u32(smu);

    // ---- stage q fp32 (into TH/TL area, stride 68) + rels ----
    const float* Qg = g_q + ((long)bh * SQ + q0) * AD;
#pragma unroll
    for (int i = 0; i < 8; i++) {
        int idx = tid + i * 256;
        int r = idx >> 4, c = idx & 15;
        cp16(sb + (uint32_t)((O_TH + r * 68 + c * 4) * 4), Qg + r * AD + c * 4);
    }
    for (int i = tid; i < 33 * 16; i += 256) {
        int r = i >> 4, c = i & 15;
        cp16(sb + (uint32_t)((O_RELS + r * 68 + c * 4) * 4), rel_emb + r * 64 + c * 4);
    }
    CP_COMMIT();

    auto load_kv = [&](int kt, int buf) {
        const uint32_t kvb = sb + (uint32_t)((O_KV + buf * 4 * KVT) * 4);
        const uint32_t* Khg = g_k_h + ((long)bh * SQ + kt * 64) * 32;
        const uint32_t* Klg = g_k_l + ((long)bh * SQ + kt * 64) * 32;
        const unsigned short* Vhg = g_vT_h + (long)bh * AD * SQ + kt * 64;
        const unsigned short* Vlg = g_vT_l + (long)bh * AD * SQ + kt * 64;
#pragma unroll
        for (int i = 0; i < 2; i++) {
            int idx = tid + i * 256;          // 0..511
            int r = idx >> 3;                 // row 0..63
            int c = idx & 7;                  // u32 quad 0..7
            uint32_t so = (uint32_t)((r * 36 + c * 4) * 4);
            cp16(kvb + 0 * KVT * 4 + so, Khg + r * 32 + c * 4);
            cp16(kvb + 1 * KVT * 4 + so, Klg + r * 32 + c * 4);
            cp16(kvb + 2 * KVT * 4 + so, Vhg + (long)r * SQ + c * 8);
            cp16(kvb + 3 * KVT * 4 + so, Vlg + (long)r * SQ + c * 8);
        }
    };
    load_kv(0, 0); CP_COMMIT();
    load_kv(1, 1); CP_COMMIT();

    CP_WAIT(2);                 // q + rels landed
    __syncthreads();

    // ---- convert q -> bf16 hi/lo in smem (once per block) ----
    float* q32 = smf + O_TH;               // [128][68] fp32
    for (int i = tid; i < 128 * 32; i += 256) {
        int r = i >> 5, c = i & 31;
        float2 v = *(const float2*)&q32[r * 68 + c * 2];
        uint32_t hi, lo;
        bsplit(v.x, v.y, hi, lo);
        smu[O_QH + r * 36 + c] = hi;
        smu[O_QL + r * 36 + c] = lo;
    }
    // ---- rq[r][p] = q_r . rel_emb[p]  (fp32) ----
    float* relf = smf + O_RELS;
    float* rqs  = smf + O_RQS;
    for (int i = tid; i < 128 * 33; i += 256) {
        int r = i / 33, p = i - r * 33;
        float s = 0.f;
#pragma unroll 16
        for (int d = 0; d < 64; d++) s = fmaf(q32[r * 68 + d], relf[p * 68 + d], s);
        rqs[r * 36 + p] = s;
    }
    __syncthreads();            // q32 reads done; TH/TL now free for t

    float oacc[8][4];
#pragma unroll
    for (int ni = 0; ni < 8; ni++)
#pragma unroll
        for (int r = 0; r < 4; r++) oacc[ni][r] = 0.f;
    float denp0 = 0.f, denp1 = 0.f;

    const uint32_t* QH = smu + O_QH;
    const uint32_t* QL = smu + O_QL;
    uint32_t* TH = smu + O_TH;
    uint32_t* TL = smu + O_TL;
    const int ig0 = q0 + mb + g;

    for (int kt = 0; kt < 16; kt++) {
        const int buf = kt & 1;
        if (kt + 1 < 16) { CP_WAIT(1); } else { CP_WAIT(0); }
        __syncthreads();
        const uint32_t* KH = smu + O_KV + (buf * 4 + 0) * KVT;
        const uint32_t* KL = smu + O_KV + (buf * 4 + 1) * KVT;
        const uint32_t* VH = smu + O_KV + (buf * 4 + 2) * KVT;
        const uint32_t* VL = smu + O_KV + (buf * 4 + 3) * KVT;

        // --- S = q k^T ; sacc[ni] covers cols ni*8 .. ni*8+7
        float sacc[8][4];
#pragma unroll
        for (int ni = 0; ni < 8; ni++)
#pragma unroll
            for (int r = 0; r < 4; r++) sacc[ni][r] = 0.f;
#pragma unroll
        for (int kk = 0; kk < 4; kk++) {
            const int kc = kk * 8;
            const int r0 = (mb + g) * 36 + kc + tig;
            const int r8 = r0 + 8 * 36;
            uint32_t ah[4], al[4];
            ah[0] = QH[r0]; ah[1] = QH[r8]; ah[2] = QH[r0 + 4]; ah[3] = QH[r8 + 4];
            al[0] = QL[r0]; al[1] = QL[r8]; al[2] = QL[r0 + 4]; al[3] = QL[r8 + 4];
#pragma unroll
            for (int ni = 0; ni < 8; ni++) {
                const int b0 = (ni * 8 + g) * 36 + kc + tig;
                uint32_t bh2[2], bl2[2];
                bh2[0] = KH[b0]; bh2[1] = KH[b0 + 4];
                bl2[0] = KL[b0]; bl2[1] = KL[b0 + 4];
                mma_bf16(sacc[ni], ah, bh2);
                mma_bf16(sacc[ni], ah, bl2);
                mma_bf16(sacc[ni], al, bh2);
            }
        }

        // --- t = relu((S + rel)/8 + b)^2 ; split once, stage hi/lo (own rows)
#pragma unroll
        for (int ni = 0; ni < 8; ni++) {
            const int cbase = ni * 8 + 2 * tig;
            const int jbase = kt * 64 + cbase;
            const int tcol = ni * 4 + tig;
            uint32_t hi, lo;
            {   // row g
                int d0 = jbase - ig0;     d0 = (d0 < -KREL) ? -KREL : ((d0 > KREL) ? KREL : d0);
                int d1 = jbase + 1 - ig0; d1 = (d1 < -KREL) ? -KREL : ((d1 > KREL) ? KREL : d1);
                float s0 = (sacc[ni][0] + rqs[(mb + g) * 36 + d0 + KREL]) * 0.125f + snb;
                float s1 = (sacc[ni][1] + rqs[(mb + g) * 36 + d1 + KREL]) * 0.125f + snb;
                s0 = fmaxf(s0, 0.f); s1 = fmaxf(s1, 0.f);
                float t0 = s0 * s0, t1 = s1 * s1;
                denp0 += t0 + t1;
                bsplit(t0, t1, hi, lo);
                TH[(mb + g) * 36 + tcol] = hi;
                TL[(mb + g) * 36 + tcol] = lo;
            }
            {   // row g+8
                int d0 = jbase - (ig0 + 8);     d0 = (d0 < -KREL) ? -KREL : ((d0 > KREL) ? KREL : d0);
                int d1 = jbase + 1 - (ig0 + 8); d1 = (d1 < -KREL) ? -KREL : ((d1 > KREL) ? KREL : d1);
                float s0 = (sacc[ni][2] + rqs[(mb + g + 8) * 36 + d0 + KREL]) * 0.125f + snb;
                float s1 = (sacc[ni][3] + rqs[(mb + g + 8) * 36 + d1 + KREL]) * 0.125f + snb;
                s0 = fmaxf(s0, 0.f); s1 = fmaxf(s1, 0.f);
                float t0 = s0 * s0, t1 = s1 * s1;
                denp1 += t0 + t1;
                bsplit(t0, t1, hi, lo);
                TH[(mb + g + 8) * 36 + tcol] = hi;
                TL[(mb + g + 8) * 36 + tcol] = lo;
            }
        }
        __syncwarp();           // own-rows handoff: warp-local only

        // --- O += t V ; oacc[ni] covers dims ni*8 .. ni*8+7
#pragma unroll
        for (int kk = 0; kk < 4; kk++) {
            const int kc = kk * 8;
            const int r0 = (mb + g) * 36 + kc + tig;
            const int r8 = r0 + 8 * 36;
            uint32_t ah[4], al[4];
            ah[0] = TH[r0]; ah[1] = TH[r8]; ah[2] = TH[r0 + 4]; ah[3] = TH[r8 + 4];
            al[0] = TL[r0]; al[1] = TL[r8]; al[2] = TL[r0 + 4]; al[3] = TL[r8 + 4];
#pragma unroll
            for (int ni = 0; ni < 8; ni++) {
                const int b0 = (ni * 8 + g) * 36 + kc + tig;
                uint32_t bh2[2], bl2[2];
                bh2[0] = VH[b0]; bh2[1] = VH[b0 + 4];
                bl2[0] = VL[b0]; bl2[1] = VL[b0 + 4];
                mma_bf16(oacc[ni], ah, bh2);
                mma_bf16(oacc[ni], ah, bl2);
                mma_bf16(oacc[ni], al, bh2);
            }
        }
        __syncthreads();        // all warps done with kv[buf] before refill
        if (kt + 2 < 16) { load_kv(kt + 2, buf); CP_COMMIT(); }
    }

    // deterministic den reduction across the 4 tig lanes
    denp0 += __shfl_xor_sync(0xffffffffu, denp0, 1);
    denp0 += __shfl_xor_sync(0xffffffffu, denp0, 2);
    denp1 += __shfl_xor_sync(0xffffffffu, denp1, 1);
    denp1 += __shfl_xor_sync(0xffffffffu, denp1, 2);
    const float inv0 = 1.f / (denp0 + SN_EPS);
    const float inv1 = 1.f / (denp1 + SN_EPS);

    // ctx written pre-split for tc_gemm<1>
    const long row0 = (long)(b * SQ + q0 + mb + g);
#pragma unroll
    for (int ni = 0; ni < 8; ni++) {
        const int c = h * 32 + ni * 4 + tig;     // u32 col in [512]
        uint32_t hi, lo;
        bsplit(oacc[ni][0] * inv0, oacc[ni][1] * inv0, hi, lo);
        g_ctx_h[row0 * 512 + c] = hi;
        g_ctx_l[row0 * 512 + c] = lo;
        bsplit(oacc[ni][2] * inv1, oacc[ni][3] * inv1, hi, lo);
        g_ctx_h[(row0 + 8) * 512 + c] = hi;
        g_ctx_l[(row0 + 8) * 512 + c] = lo;
    }
}

// ===========================================================================
extern "C" void kernel_launch(void* const* d_in, const int* in_sizes, int n_in,
                              void* d_out, int out_size)
{
    (void)in_sizes; (void)n_in; (void)out_size;
    const float* iQ  = (const float*)d_in[0];
    const float* Wa  = (const float*)d_in[1];
    const float* ba  = (const float*)d_in[2];
    const float* rel = (const float*)d_in[3];
    const float* snb = (const float*)d_in[4];
    const float* Wo  = (const float*)d_in[5];
    const float* bo  = (const float*)d_in[6];
    float* out = (float*)d_out;

    cudaFuncSetAttribute(tc_gemm<0>, cudaFuncAttributeMaxDynamicSharedMemorySize, GSM_BYTES);
    cudaFuncSetAttribute(tc_gemm<1>, cudaFuncAttributeMaxDynamicSharedMemorySize, GSM_BYTES);
    cudaFuncSetAttribute(attn_mma,   cudaFuncAttributeMaxDynamicSharedMemorySize, A_BYTES);

    uint32_t *iQh, *iQl, *Wah, *Wal, *Woh, *Wol;
    cudaGetSymbolAddress((void**)&iQh, g_iQ_h); cudaGetSymbolAddress((void**)&iQl, g_iQ_l);
    cudaGetSymbolAddress((void**)&Wah, g_Wa_h); cudaGetSymbolAddress((void**)&Wal, g_Wa_l);
    cudaGetSymbolAddress((void**)&Woh, g_Wo_h); cudaGetSymbolAddress((void**)&Wol, g_Wo_l);

    // 0) pre-split inputs to packed bf16 hi/lo
    cvt_kernel<<<2048, 256>>>(iQ, iQh, iQl, 4096 * 512);
    cvt_kernel<<<2048, 256>>>(Wa, Wah, Wal, 3072 * 512);
    cvt_kernel<<<1024, 256>>>(Wo, Woh, Wol, 1024 * 512);

    // 1) QKV projection -> g_q (fp32), g_k hi/lo, g_vT hi/lo
    tc_gemm<0><<<dim3(3072 / 128, 4096 / 128), 256, GSM_BYTES>>>(iQh, iQl, Wah, Wal, ba, nullptr, 3072);

    // 2) tensor-core attention + SparseNormer -> g_ctx hi/lo
    attn_mma<<<dim3(SQ / 128, HN, NB), 256, A_BYTES>>>(rel, snb);

    // 3) output projection -> out
    {
        uint32_t *ch, *cl;
        cudaGetSymbolAddress((void**)&ch, g_ctx_h);
        cudaGetSymbolAddress((void**)&cl, g_ctx_l);
        tc_gemm<1><<<dim3(1024 / 128, 4096 / 128), 256, GSM_BYTES>>>(ch, cl, Woh, Wol, bo, out, 1024);
    }
}

// round 14
// speedup vs baseline: 2.4064x; 1.0687x over previous
#include <cuda_runtime.h>
#include <cstdint>

// Problem constants
#define HN    16
#define AD    64
#define SQ    1024
#define NB    4
#define DM    1024
#define KREL  16
#define SN_EPS 1e-8f

// ---------------------------------------------------------------------------
// Scratch (device globals: no runtime allocation allowed).
// Packed bf16x2 convention: u32 = [bf16(x_even) low | bf16(x_odd) high],
// pairs along the K-contiguous dimension.
// ---------------------------------------------------------------------------
__device__ __align__(16) float    g_q   [NB * HN * SQ * AD];      // fp32 (rq needs it)
__device__ __align__(16) uint32_t g_k_h [NB * HN * SQ * AD / 2];  // [B,H,S,32] pairs along d
__device__ __align__(16) uint32_t g_k_l [NB * HN * SQ * AD / 2];
__device__ __align__(16) unsigned short g_vT_h[NB * HN * AD * SQ]; // [B,H,AD,S] transposed
__device__ __align__(16) unsigned short g_vT_l[NB * HN * AD * SQ];
__device__ __align__(16) uint32_t g_ctx_h[NB * SQ * DM / 2];      // [B,S,512]
__device__ __align__(16) uint32_t g_ctx_l[NB * SQ * DM / 2];
__device__ __align__(16) uint32_t g_iQ_h[4096 * 512];
__device__ __align__(16) uint32_t g_iQ_l[4096 * 512];
__device__ __align__(16) uint32_t g_Wa_h[3072 * 512];
__device__ __align__(16) uint32_t g_Wa_l[3072 * 512];
__device__ __align__(16) uint32_t g_Wo_h[1024 * 512];
__device__ __align__(16) uint32_t g_Wo_l[1024 * 512];

// ===========================================================================
// Helpers (baseline sm_80+ PTX only)
// ===========================================================================
__device__ __forceinline__ void cp16(uint32_t saddr, const void* g) {
    asm volatile("cp.async.cg.shared.global [%0], [%1], 16;\n" :: "r"(saddr), "l"(g));
}
#define CP_COMMIT() asm volatile("cp.async.commit_group;\n" ::: "memory")
#define CP_WAIT(n)  asm volatile("cp.async.wait_group %0;\n" :: "n"(n) : "memory")

__device__ __forceinline__ uint32_t smem_u32(const void* p) {
    uint32_t a;
    asm("{ .reg .u64 t; cvta.to.shared.u64 t, %1; cvt.u32.u64 %0, t; }"
        : "=r"(a) : "l"(p));
    return a;
}

__device__ __forceinline__ void mma_bf16(float c[4], const uint32_t a[4], const uint32_t b[2]) {
    asm volatile(
        "mma.sync.aligned.m16n8k16.row.col.f32.bf16.bf16.f32 "
        "{%0,%1,%2,%3}, {%4,%5,%6,%7}, {%8,%9}, {%0,%1,%2,%3};"
        : "+f"(c[0]), "+f"(c[1]), "+f"(c[2]), "+f"(c[3])
        : "r"(a[0]), "r"(a[1]), "r"(a[2]), "r"(a[3]), "r"(b[0]), "r"(b[1]));
}

// hi_i = bf16-truncate(x_i) (exact), lo_i = x_i - hi_i (|lo|<=2^-8|x|, bf16
// re-truncation residual <= 2^-16 |x|). Packed [x0 | x1].
__device__ __forceinline__ void bsplit(float x0, float x1, uint32_t& hi, uint32_t& lo) {
    uint32_t h0 = __float_as_uint(x0) & 0xFFFF0000u;
    uint32_t h1 = __float_as_uint(x1) & 0xFFFF0000u;
    hi = __byte_perm(h0, h1, 0x7632);
    float l0 = x0 - __uint_as_float(h0);
    float l1 = x1 - __uint_as_float(h1);
    lo = __byte_perm(__float_as_uint(l0), __float_as_uint(l1), 0x7632);
}

// ===========================================================================
// fp32 -> packed bf16x2 hi/lo converter (bandwidth-bound, grid-stride)
// ===========================================================================
__global__ void cvt_kernel(const float* __restrict__ src, uint32_t* __restrict__ h,
                           uint32_t* __restrict__ l, int npairs)
{
    for (int i = blockIdx.x * blockDim.x + threadIdx.x; i < npairs;
         i += gridDim.x * blockDim.x) {
        float2 v = ((const float2*)src)[i];
        uint32_t hi, lo;
        bsplit(v.x, v.y, hi, lo);
        h[i] = hi;
        l[i] = lo;
    }
}

// ===========================================================================
// 3xBF16 GEMM on PRE-SPLIT operands (unchanged from round 13 — known good)
// ===========================================================================
#define GKU    512
#define ROWU   20
#define TILEU  (128 * ROWU)
#define GSM_BYTES (2 * 4 * TILEU * 4)      // 2 buf x 4 tiles (Ah,Al,Wh,Wl)

template <int MODE>
__global__ __launch_bounds__(256, 2)
void tc_gemm(const uint32_t* __restrict__ Ahg, const uint32_t* __restrict__ Alg,
             const uint32_t* __restrict__ Whg, const uint32_t* __restrict__ Wlg,
             const float* __restrict__ bias, float* __restrict__ C, int N)
{
    extern __shared__ __align__(16) uint32_t smu[];

    const int tid  = threadIdx.x;
    const int wid  = tid >> 5;
    const int lane = tid & 31;
    const int g    = lane >> 2;
    const int tig  = lane & 3;
    const int wm   = wid >> 2;
    const int wn   = wid & 3;
    const int mbase = wm * 64;
    const int nbase = wn * 32;

    const int bx = blockIdx.x;
    const int by = blockIdx.y;

    const uint32_t* srcs[4] = {
        Ahg + (long)(by * 128) * GKU, Alg + (long)(by * 128) * GKU,
        Whg + (long)(bx * 128) * GKU, Wlg + (long)(bx * 128) * GKU };

    const uint32_t sbase = smem_u32(smu);
    auto load_chunk = [&](int kc, int buf) {
#pragma unroll
        for (int t = 0; t < 4; t++) {
#pragma unroll
            for (int i = 0; i < 2; i++) {
                int idx = tid + i * 256;          // 0..511
                int r = idx >> 2;                 // row 0..127
                int q = idx & 3;                  // u32 quad
                cp16(sbase + (uint32_t)(((buf * 4 + t) * TILEU + r * ROWU + q * 4) * 4),
                     srcs[t] + (long)r * GKU + kc * 16 + q * 4);
            }
        }
    };

    float acc[4][4][4];
#pragma unroll
    for (int mi = 0; mi < 4; mi++)
#pragma unroll
        for (int ni = 0; ni < 4; ni++)
#pragma unroll
            for (int r = 0; r < 4; r++) acc[mi][ni][r] = 0.f;

    load_chunk(0, 0); CP_COMMIT();
    load_chunk(1, 1); CP_COMMIT();

    const int NCH = 32;                    // 1024 / 32
    for (int k0 = 0; k0 < NCH; k0++) {
        const int buf = k0 & 1;
        if (k0 + 1 < NCH) { CP_WAIT(1); } else { CP_WAIT(0); }
        __syncthreads();

        const uint32_t* Ah = smu + (buf * 4 + 0) * TILEU;
        const uint32_t* Al = smu + (buf * 4 + 1) * TILEU;
        const uint32_t* Wh = smu + (buf * 4 + 2) * TILEU;
        const uint32_t* Wl = smu + (buf * 4 + 3) * TILEU;
#pragma unroll
        for (int kk = 0; kk < 2; kk++) {
            const int kc = kk * 8;
            uint32_t bh[4][2], bl[4][2];
#pragma unroll
            for (int ni = 0; ni < 4; ni++) {
                const int r0 = (nbase + ni * 8 + g) * ROWU + kc + tig;
                bh[ni][0] = Wh[r0];     bh[ni][1] = Wh[r0 + 4];
                bl[ni][0] = Wl[r0];     bl[ni][1] = Wl[r0 + 4];
            }
#pragma unroll
            for (int mi = 0; mi < 4; mi++) {
                const int r0 = (mbase + mi * 16 + g) * ROWU + kc + tig;
                const int r8 = r0 + 8 * ROWU;
                uint32_t ah[4], al[4];
                ah[0] = Ah[r0]; ah[1] = Ah[r8]; ah[2] = Ah[r0 + 4]; ah[3] = Ah[r8 + 4];
                al[0] = Al[r0]; al[1] = Al[r8]; al[2] = Al[r0 + 4]; al[3] = Al[r8 + 4];
#pragma unroll
                for (int ni = 0; ni < 4; ni++) {
                    mma_bf16(acc[mi][ni], ah, bh[ni]);
                    mma_bf16(acc[mi][ni], ah, bl[ni]);
                    mma_bf16(acc[mi][ni], al, bh[ni]);
                }
            }
        }
        __syncthreads();
        if (k0 + 2 < NCH) { load_chunk(k0 + 2, buf); CP_COMMIT(); }
    }

    // Epilogue: c-frag (m16n8) rows g,g+8; cols 2tig,2tig+1 (adjacent pair)
#pragma unroll
    for (int ni = 0; ni < 4; ni++) {
        const int gcol = bx * 128 + nbase + ni * 8 + 2 * tig;
        const float b0 = bias[gcol];
        const float b1 = bias[gcol + 1];
        const int which = gcol >> 10;
        const int hh = (gcol >> 6) & 15;
        const int dd = gcol & 63;
#pragma unroll
        for (int mi = 0; mi < 4; mi++) {
#pragma unroll
            for (int h = 0; h < 2; h++) {
                const int rr = by * 128 + mbase + mi * 16 + g + h * 8;
                float2 o;
                o.x = acc[mi][ni][2 * h + 0] + b0;
                o.y = acc[mi][ni][2 * h + 1] + b1;
                if (MODE == 0) {
                    const int bb = rr >> 10, ss = rr & 1023;
                    const long bhq = (long)(bb * HN + hh);
                    if (which == 0) {
                        *(float2*)(g_q + (bhq * SQ + ss) * AD + dd) = o;
                    } else if (which == 1) {
                        uint32_t hi, lo;
                        bsplit(o.x, o.y, hi, lo);
                        const long idx = (bhq * SQ + ss) * 32 + (dd >> 1);
                        g_k_h[idx] = hi;
                        g_k_l[idx] = lo;
                    } else {
                        uint32_t hi, lo;
                        bsplit(o.x, o.y, hi, lo);
                        const long base = (bhq * AD + dd) * SQ + ss;
                        g_vT_h[base]      = (unsigned short)(hi & 0xFFFFu);
                        g_vT_h[base + SQ] = (unsigned short)(hi >> 16);
                        g_vT_l[base]      = (unsigned short)(lo & 0xFFFFu);
                        g_vT_l[base + SQ] = (unsigned short)(lo >> 16);
                    }
                } else {
                    *(float2*)(C + (long)rr * N + gcol) = o;
                }
            }
        }
    }
}

// ===========================================================================
// Tensor-core attention, register P-reuse (no t smem roundtrip).
// Grid (8,16,4), 256 thr, q tile 128 rows (warp w owns [16w,16w+16)).
// kv tiles 32 rows, double-buffered. S c-frag IS the PV A-frag (same lane):
//   a[kk2] = { sacc[2kk2], sacc[2kk2+1] } after elementwise + bsplit.
// smem ~103 KB -> 2 CTAs/SM.
// ===========================================================================
#define O_QH   0                              // [128][36]
#define O_QL   (O_QH + 128*36)                // 4608
#define O_KV   (O_QL + 128*36)                // 2 buf x 4864
#define KVBUF  4864                           // KH[32][36] KL[32][36] VH[64][20] VL[64][20]
#define KV_KH  0
#define KV_KL  1152
#define KV_VH  2304
#define KV_VL  3584
#define O_RELS (O_KV + 2*KVBUF)               // fp32 [33][68]
#define O_RQS  (O_RELS + 33*68)               // fp32 [128][36]
#define A_TOTU (O_RQS + 128*36)
#define A_BYTES (A_TOTU * 4)                  // 103,184 B -> 2 CTAs/SM

__global__ __launch_bounds__(256, 2)
void attn_mma(const float* __restrict__ rel_emb, const float* __restrict__ snb_p)
{
    extern __shared__ __align__(16) uint32_t smu[];
    float* smf = (float*)smu;

    const int tid  = threadIdx.x;
    const int wid  = tid >> 5;
    const int lane = tid & 31;
    const int g    = lane >> 2;
    const int tig  = lane & 3;
    const int qt = blockIdx.x, h = blockIdx.y, b = blockIdx.z;
    const int bh = b * HN + h;
    const int q0 = qt * 128;
    const int mb = wid * 16;
    const float snb = __ldg(snb_p);

    const uint32_t sb = smem_u32(smu);

    // ---- preamble: stage q fp32 (transiently in KV area, stride 68) + rels
    const float* Qg = g_q + ((long)bh * SQ + q0) * AD;
#pragma unroll
    for (int i = 0; i < 8; i++) {
        int idx = tid + i * 256;
        int r = idx >> 4, c = idx & 15;
        cp16(sb + (uint32_t)((O_KV + r * 68 + c * 4) * 4), Qg + r * AD + c * 4);
    }
    for (int i = tid; i < 33 * 16; i += 256) {
        int r = i >> 4, c = i & 15;
        cp16(sb + (uint32_t)((O_RELS + r * 68 + c * 4) * 4), rel_emb + r * 64 + c * 4);
    }
    CP_COMMIT();
    CP_WAIT(0);
    __syncthreads();

    // q -> bf16 hi/lo (once per block)
    float* q32 = smf + O_KV;                 // [128][68] fp32 (transient)
    for (int i = tid; i < 128 * 32; i += 256) {
        int r = i >> 5, c = i & 31;
        float2 v = *(const float2*)&q32[r * 68 + c * 2];
        uint32_t hi, lo;
        bsplit(v.x, v.y, hi, lo);
        smu[O_QH + r * 36 + c] = hi;
        smu[O_QL + r * 36 + c] = lo;
    }
    // rq[r][p] = q_r . rel_emb[p]  (fp32)
    float* relf = smf + O_RELS;
    float* rqs  = smf + O_RQS;
    for (int i = tid; i < 128 * 33; i += 256) {
        int r = i / 33, p = i - r * 33;
        float s = 0.f;
#pragma unroll 16
        for (int d = 0; d < 64; d++) s = fmaf(q32[r * 68 + d], relf[p * 68 + d], s);
        rqs[r * 36 + p] = s;
    }
    __syncthreads();            // q32 reads done; KV area now free

    auto load_kv = [&](int kt, int buf) {
        const uint32_t kvb = sb + (uint32_t)((O_KV + buf * KVBUF) * 4);
        const uint32_t* Khg = g_k_h + ((long)bh * SQ + kt * 32) * 32;
        const uint32_t* Klg = g_k_l + ((long)bh * SQ + kt * 32) * 32;
        const unsigned short* Vhg = g_vT_h + (long)bh * AD * SQ + kt * 32;
        const unsigned short* Vlg = g_vT_l + (long)bh * AD * SQ + kt * 32;
        {   // K tiles: 32 rows x 8 quads, 256 threads -> 1 each per tile
            int r = tid >> 3, c = tid & 7;
            uint32_t so = (uint32_t)((r * 36 + c * 4) * 4);
            cp16(kvb + KV_KH * 4 + so, Khg + r * 32 + c * 4);
            cp16(kvb + KV_KL * 4 + so, Klg + r * 32 + c * 4);
        }
        {   // V tiles: 64 d-rows x 4 quads (16 u32 = 32 shorts along s)
            int d = tid >> 2, c = tid & 3;
            uint32_t so = (uint32_t)((d * 20 + c * 4) * 4);
            cp16(kvb + KV_VH * 4 + so, Vhg + (long)d * SQ + c * 8);
            cp16(kvb + KV_VL * 4 + so, Vlg + (long)d * SQ + c * 8);
        }
    };
    load_kv(0, 0); CP_COMMIT();
    load_kv(1, 1); CP_COMMIT();

    float oacc[8][4];
#pragma unroll
    for (int ni = 0; ni < 8; ni++)
#pragma unroll
        for (int r = 0; r < 4; r++) oacc[ni][r] = 0.f;
    float denp0 = 0.f, denp1 = 0.f;

    const uint32_t* QH = smu + O_QH;
    const uint32_t* QL = smu + O_QL;
    const int ig0 = q0 + mb + g;

    for (int kt = 0; kt < 32; kt++) {
        const int buf = kt & 1;
        if (kt + 1 < 32) { CP_WAIT(1); } else { CP_WAIT(0); }
        __syncthreads();
        const uint32_t* KH = smu + O_KV + buf * KVBUF + KV_KH;
        const uint32_t* KL = smu + O_KV + buf * KVBUF + KV_KL;
        const uint32_t* VH = smu + O_KV + buf * KVBUF + KV_VH;
        const uint32_t* VL = smu + O_KV + buf * KVBUF + KV_VL;

        // --- S = q k^T over 32 key rows; sacc[ni] covers cols ni*8..+7
        float sacc[4][4];
#pragma unroll
        for (int ni = 0; ni < 4; ni++)
#pragma unroll
            for (int r = 0; r < 4; r++) sacc[ni][r] = 0.f;
#pragma unroll
        for (int kk = 0; kk < 4; kk++) {
            const int kc = kk * 8;
            const int r0 = (mb + g) * 36 + kc + tig;
            const int r8 = r0 + 8 * 36;
            uint32_t ah[4], al[4];
            ah[0] = QH[r0]; ah[1] = QH[r8]; ah[2] = QH[r0 + 4]; ah[3] = QH[r8 + 4];
            al[0] = QL[r0]; al[1] = QL[r8]; al[2] = QL[r0 + 4]; al[3] = QL[r8 + 4];
#pragma unroll
            for (int ni = 0; ni < 4; ni++) {
                const int b0 = (ni * 8 + g) * 36 + kc + tig;
                uint32_t bh2[2], bl2[2];
                bh2[0] = KH[b0]; bh2[1] = KH[b0 + 4];
                bl2[0] = KL[b0]; bl2[1] = KL[b0 + 4];
                mma_bf16(sacc[ni], ah, bh2);
                mma_bf16(sacc[ni], ah, bl2);
                mma_bf16(sacc[ni], al, bh2);
            }
        }

        // --- elementwise in registers: t = relu((S+rel)/8 + b)^2, split ---
        // tha[ni]/tla[ni]: packed pair rows g; thb/tlb: rows g+8
        uint32_t tha[4], tla[4], thb[4], tlb[4];
#pragma unroll
        for (int ni = 0; ni < 4; ni++) {
            const int cbase = ni * 8 + 2 * tig;
            const int jbase = kt * 32 + cbase;
            {   // row g
                int d0 = jbase - ig0;     d0 = (d0 < -KREL) ? -KREL : ((d0 > KREL) ? KREL : d0);
                int d1 = jbase + 1 - ig0; d1 = (d1 < -KREL) ? -KREL : ((d1 > KREL) ? KREL : d1);
                float s0 = (sacc[ni][0] + rqs[(mb + g) * 36 + d0 + KREL]) * 0.125f + snb;
                float s1 = (sacc[ni][1] + rqs[(mb + g) * 36 + d1 + KREL]) * 0.125f + snb;
                s0 = fmaxf(s0, 0.f); s1 = fmaxf(s1, 0.f);
                float t0 = s0 * s0, t1 = s1 * s1;
                denp0 += t0 + t1;
                bsplit(t0, t1, tha[ni], tla[ni]);
            }
            {   // row g+8
                int d0 = jbase - (ig0 + 8);     d0 = (d0 < -KREL) ? -KREL : ((d0 > KREL) ? KREL : d0);
                int d1 = jbase + 1 - (ig0 + 8); d1 = (d1 < -KREL) ? -KREL : ((d1 > KREL) ? KREL : d1);
                float s0 = (sacc[ni][2] + rqs[(mb + g + 8) * 36 + d0 + KREL]) * 0.125f + snb;
                float s1 = (sacc[ni][3] + rqs[(mb + g + 8) * 36 + d1 + KREL]) * 0.125f + snb;
                s0 = fmaxf(s0, 0.f); s1 = fmaxf(s1, 0.f);
                float t0 = s0 * s0, t1 = s1 * s1;
                denp1 += t0 + t1;
                bsplit(t0, t1, thb[ni], tlb[ni]);
            }
        }

        // --- O += t V ; A-frag is the in-register t (no smem roundtrip) ---
#pragma unroll
        for (int kk2 = 0; kk2 < 2; kk2++) {
            uint32_t ah[4], al[4];
            ah[0] = tha[2 * kk2];     al[0] = tla[2 * kk2];
            ah[1] = thb[2 * kk2];     al[1] = tlb[2 * kk2];
            ah[2] = tha[2 * kk2 + 1]; al[2] = tla[2 * kk2 + 1];
            ah[3] = thb[2 * kk2 + 1]; al[3] = tlb[2 * kk2 + 1];
#pragma unroll
            for (int ni = 0; ni < 8; ni++) {
                const int b0 = (ni * 8 + g) * 20 + kk2 * 8 + tig;
                uint32_t bh2[2], bl2[2];
                bh2[0] = VH[b0]; bh2[1] = VH[b0 + 4];
                bl2[0] = VL[b0]; bl2[1] = VL[b0 + 4];
                mma_bf16(oacc[ni], ah, bh2);
                mma_bf16(oacc[ni], ah, bl2);
                mma_bf16(oacc[ni], al, bh2);
            }
        }
        __syncthreads();        // all warps done with kv[buf] before refill
        if (kt + 2 < 32) { load_kv(kt + 2, buf); CP_COMMIT(); }
    }

    // deterministic den reduction across the 4 tig lanes
    denp0 += __shfl_xor_sync(0xffffffffu, denp0, 1);
    denp0 += __shfl_xor_sync(0xffffffffu, denp0, 2);
    denp1 += __shfl_xor_sync(0xffffffffu, denp1, 1);
    denp1 += __shfl_xor_sync(0xffffffffu, denp1, 2);
    const float inv0 = 1.f / (denp0 + SN_EPS);
    const float inv1 = 1.f / (denp1 + SN_EPS);

    // ctx written pre-split for tc_gemm<1>
    const long row0 = (long)(b * SQ + q0 + mb + g);
#pragma unroll
    for (int ni = 0; ni < 8; ni++) {
        const int c = h * 32 + ni * 4 + tig;     // u32 col in [512]
        uint32_t hi, lo;
        bsplit(oacc[ni][0] * inv0, oacc[ni][1] * inv0, hi, lo);
        g_ctx_h[row0 * 512 + c] = hi;
        g_ctx_l[row0 * 512 + c] = lo;
        bsplit(oacc[ni][2] * inv1, oacc[ni][3] * inv1, hi, lo);
        g_ctx_h[(row0 + 8) * 512 + c] = hi;
        g_ctx_l[(row0 + 8) * 512 + c] = lo;
    }
}

// ===========================================================================
extern "C" void kernel_launch(void* const* d_in, const int* in_sizes, int n_in,
                              void* d_out, int out_size)
{
    (void)in_sizes; (void)n_in; (void)out_size;
    const float* iQ  = (const float*)d_in[0];
    const float* Wa  = (const float*)d_in[1];
    const float* ba  = (const float*)d_in[2];
    const float* rel = (const float*)d_in[3];
    const float* snb = (const float*)d_in[4];
    const float* Wo  = (const float*)d_in[5];
    const float* bo  = (const float*)d_in[6];
    float* out = (float*)d_out;

    cudaFuncSetAttribute(tc_gemm<0>, cudaFuncAttributeMaxDynamicSharedMemorySize, GSM_BYTES);
    cudaFuncSetAttribute(tc_gemm<1>, cudaFuncAttributeMaxDynamicSharedMemorySize, GSM_BYTES);
    cudaFuncSetAttribute(attn_mma,   cudaFuncAttributeMaxDynamicSharedMemorySize, A_BYTES);

    uint32_t *iQh, *iQl, *Wah, *Wal, *Woh, *Wol;
    cudaGetSymbolAddress((void**)&iQh, g_iQ_h); cudaGetSymbolAddress((void**)&iQl, g_iQ_l);
    cudaGetSymbolAddress((void**)&Wah, g_Wa_h); cudaGetSymbolAddress((void**)&Wal, g_Wa_l);
    cudaGetSymbolAddress((void**)&Woh, g_Wo_h); cudaGetSymbolAddress((void**)&Wol, g_Wo_l);

    // 0) pre-split inputs to packed bf16 hi/lo
    cvt_kernel<<<2048, 256>>>(iQ, iQh, iQl, 4096 * 512);
    cvt_kernel<<<2048, 256>>>(Wa, Wah, Wal, 3072 * 512);
    cvt_kernel<<<1024, 256>>>(Wo, Woh, Wol, 1024 * 512);

    // 1) QKV projection -> g_q (fp32), g_k hi/lo, g_vT hi/lo
    tc_gemm<0><<<dim3(3072 / 128, 4096 / 128), 256, GSM_BYTES>>>(iQh, iQl, Wah, Wal, ba, nullptr, 3072);

    // 2) tensor-core attention + SparseNormer -> g_ctx hi/lo
    attn_mma<<<dim3(SQ / 128, HN, NB), 256, A_BYTES>>>(rel, snb);

    // 3) output projection -> out
    {
        uint32_t *ch, *cl;
        cudaGetSymbolAddress((void**)&ch, g_ctx_h);
        cudaGetSymbolAddress((void**)&cl, g_ctx_l);
        tc_gemm<1><<<dim3(1024 / 128, 4096 / 128), 256, GSM_BYTES>>>(ch, cl, Woh, Wol, bo, out, 1024);
    }
}